// round 1
// baseline (speedup 1.0000x reference)
#include <cuda_runtime.h>
#include <math.h>

// ---------------- problem constants ----------------
#define BB     16
#define CC     128
#define TT     294
#define VV     25
#define NTOK   (BB*TT*VV)        // 117600 tokens
#define INNER  512
#define NHEAD  8
#define DH     64
#define PP     7
#define NTP    42                 // T / P
#define NKTOK  (BB*NTP*VV)        // 16800 kv tokens (global)
#define SCALE_ATT 0.125f
#define LN_EPS 1e-5f

// ---------------- scratch (static device memory; no allocs) ----------------
__device__ float g_xT[NTOK*CC];        // residual stream, token-major [N,128]
__device__ float g_xn[NTOK*CC];        // layernorm output
__device__ float g_q [NTOK*INNER];     // q buffer / ff hidden [N,512]
__device__ float g_kv[NTOK*2*INNER];   // local kv [N,1024]; global kv [16800,1024]
__device__ float g_ao[NTOK*INNER];     // attention output [N,512]
__device__ float g_xg[NKTOK*896];      // gathered input for global kv gemm

// ---------------- transpose in: x[B,C,T,V] -> xT[(b t v), c] ----------------
__global__ void k_tin(const float* __restrict__ x) {
    int bt = blockIdx.x;
    int t = bt % TT, b = bt / TT;
    __shared__ float sm[CC*VV];  // sm[c*25+v]
    for (int idx = threadIdx.x; idx < CC*VV; idx += blockDim.x) {
        int c = idx / VV, v = idx % VV;
        sm[idx] = x[(((size_t)b*CC + c)*TT + t)*VV + v];
    }
    __syncthreads();
    size_t base = ((size_t)(b*TT + t))*VV*CC;
    for (int idx = threadIdx.x; idx < CC*VV; idx += blockDim.x) {
        int v = idx / CC, c = idx % CC;   // idx = v*128 + c  (coalesced write)
        g_xT[base + idx] = sm[c*VV + v];
    }
}

// ---------------- transpose out ----------------
__global__ void k_tout(float* __restrict__ out) {
    int bt = blockIdx.x;
    int t = bt % TT, b = bt / TT;
    __shared__ float sm[CC*VV];  // sm[v*128+c]
    size_t base = ((size_t)(b*TT + t))*VV*CC;
    for (int idx = threadIdx.x; idx < CC*VV; idx += blockDim.x)
        sm[idx] = g_xT[base + idx];
    __syncthreads();
    for (int idx = threadIdx.x; idx < CC*VV; idx += blockDim.x) {
        int c = idx / VV, v = idx % VV;
        out[(((size_t)b*CC + c)*TT + t)*VV + v] = sm[v*CC + c];
    }
}

// ---------------- channel layernorm: one warp per token ----------------
__global__ void __launch_bounds__(256) k_ln(const float* __restrict__ gam,
                                            const float* __restrict__ bet) {
    int n = blockIdx.x * 8 + (threadIdx.x >> 5);
    if (n >= NTOK) return;
    int lane = threadIdx.x & 31;
    float4 a = ((const float4*)(g_xT + (size_t)n*CC))[lane];
    float s  = a.x + a.y + a.z + a.w;
    float ss = a.x*a.x + a.y*a.y + a.z*a.z + a.w*a.w;
    #pragma unroll
    for (int o = 16; o; o >>= 1) {
        s  += __shfl_xor_sync(0xffffffffu, s,  o);
        ss += __shfl_xor_sync(0xffffffffu, ss, o);
    }
    float m   = s * (1.f/128.f);
    float var = ss * (1.f/128.f) - m*m;
    float r   = rsqrtf(var + LN_EPS);
    float4 gg = ((const float4*)gam)[lane];
    float4 bb = ((const float4*)bet)[lane];
    float4 o4;
    o4.x = (a.x - m)*r*gg.x + bb.x;
    o4.y = (a.y - m)*r*gg.y + bb.y;
    o4.z = (a.z - m)*r*gg.z + bb.z;
    o4.w = (a.w - m)*r*gg.w + bb.w;
    ((float4*)(g_xn + (size_t)n*CC))[lane] = o4;
}

// ---------------- generic SGEMM: C[N,M] = A[N,K] @ W[K,M] (+epilogue) -------
// EPI: 0 = none, 2 = bias+gelu(exact), 3 = bias+residual
__device__ __forceinline__ float gelu_exact(float v) {
    return 0.5f * v * (1.0f + erff(v * 0.7071067811865475f));
}

template<int EPI>
__global__ void __launch_bounds__(256) k_gemm(
    const float* __restrict__ A, const float* __restrict__ W,
    const float* __restrict__ bias, const float* __restrict__ res,
    float* __restrict__ C, int Nrows, int K, int M)
{
    __shared__ float As[16][64];
    __shared__ float Bs[16][64];
    const int tid = threadIdx.x;
    const int rowBase = blockIdx.y << 6;
    const int colBase = blockIdx.x << 6;
    const int ar = tid >> 2;          // A row within tile
    const int ak = (tid & 3) << 2;    // A k offset
    const int bk = tid >> 4;          // B k row
    const int bm = (tid & 15) << 2;   // B m offset
    const int ty = tid >> 4;
    const int tx = tid & 15;
    float acc[4][4] = {};
    const int arow = rowBase + ar;
    const bool arok = (arow < Nrows);
    const float* Aptr = A + (size_t)(arok ? arow : 0) * K + ak;
    const float* Wptr = W + (size_t)bk * M + colBase + bm;
    for (int k0 = 0; k0 < K; k0 += 16) {
        float4 av = arok ? *(const float4*)(Aptr + k0)
                         : make_float4(0.f, 0.f, 0.f, 0.f);
        As[ak+0][ar] = av.x; As[ak+1][ar] = av.y;
        As[ak+2][ar] = av.z; As[ak+3][ar] = av.w;
        *(float4*)&Bs[bk][bm] = *(const float4*)(Wptr + (size_t)k0 * M);
        __syncthreads();
        #pragma unroll
        for (int k = 0; k < 16; ++k) {
            float4 a4 = *(const float4*)&As[k][ty << 2];
            float4 b4 = *(const float4*)&Bs[k][tx << 2];
            acc[0][0] += a4.x*b4.x; acc[0][1] += a4.x*b4.y; acc[0][2] += a4.x*b4.z; acc[0][3] += a4.x*b4.w;
            acc[1][0] += a4.y*b4.x; acc[1][1] += a4.y*b4.y; acc[1][2] += a4.y*b4.z; acc[1][3] += a4.y*b4.w;
            acc[2][0] += a4.z*b4.x; acc[2][1] += a4.z*b4.y; acc[2][2] += a4.z*b4.z; acc[2][3] += a4.z*b4.w;
            acc[3][0] += a4.w*b4.x; acc[3][1] += a4.w*b4.y; acc[3][2] += a4.w*b4.z; acc[3][3] += a4.w*b4.w;
        }
        __syncthreads();
    }
    const int row0 = rowBase + (ty << 2);
    const int col0 = colBase + (tx << 2);
    float4 bv = make_float4(0.f, 0.f, 0.f, 0.f);
    if (EPI >= 1) bv = *(const float4*)(bias + col0);
    #pragma unroll
    for (int i = 0; i < 4; ++i) {
        int r = row0 + i;
        if (r >= Nrows) continue;
        float4 o;
        o.x = acc[i][0] + bv.x; o.y = acc[i][1] + bv.y;
        o.z = acc[i][2] + bv.z; o.w = acc[i][3] + bv.w;
        if (EPI == 2) {
            o.x = gelu_exact(o.x); o.y = gelu_exact(o.y);
            o.z = gelu_exact(o.z); o.w = gelu_exact(o.w);
        }
        if (EPI == 3) {
            float4 rv = *(const float4*)(res + (size_t)r*M + col0);
            o.x += rv.x; o.y += rv.y; o.z += rv.z; o.w += rv.w;
        }
        *(float4*)(C + (size_t)r*M + col0) = o;
    }
}

// ---------------- local attention: one warp per (b, patch, v, head) --------
__global__ void __launch_bounds__(256) k_lattn() {
    int w = blockIdx.x * 8 + (threadIdx.x >> 5);   // 0 .. 134399
    int lane = threadIdx.x & 31;
    int h = w & 7;
    int g = w >> 3;                // (b, tt, v)
    int v = g % VV;
    int r = g / VV;
    int tt = r % NTP;
    int b = r / NTP;
    int d0 = lane * 2;

    float2 q[PP], kk[PP], vv[PP];
    #pragma unroll
    for (int p = 0; p < PP; ++p) {
        int n = (b*TT + tt*PP + p)*VV + v;
        q[p]  = *(const float2*)(g_q  + (size_t)n*INNER + h*DH + d0);
        size_t ko = (size_t)n*(2*INNER) + h*DH + d0;
        kk[p] = *(const float2*)(g_kv + ko);
        vv[p] = *(const float2*)(g_kv + ko + INNER);
    }
    float dots[PP][PP];
    #pragma unroll
    for (int i = 0; i < PP; ++i)
        #pragma unroll
        for (int j = 0; j < PP; ++j)
            dots[i][j] = q[i].x*kk[j].x + q[i].y*kk[j].y;
    #pragma unroll
    for (int o = 16; o; o >>= 1)
        #pragma unroll
        for (int i = 0; i < PP; ++i)
            #pragma unroll
            for (int j = 0; j < PP; ++j)
                dots[i][j] += __shfl_xor_sync(0xffffffffu, dots[i][j], o);
    // softmax per row (redundant across lanes, cheap)
    #pragma unroll
    for (int i = 0; i < PP; ++i) {
        float mx = -1e30f;
        #pragma unroll
        for (int j = 0; j < PP; ++j) {
            dots[i][j] *= SCALE_ATT;
            mx = fmaxf(mx, dots[i][j]);
        }
        float s = 0.f;
        #pragma unroll
        for (int j = 0; j < PP; ++j) { dots[i][j] = __expf(dots[i][j] - mx); s += dots[i][j]; }
        float inv = 1.f / s;
        #pragma unroll
        for (int j = 0; j < PP; ++j) dots[i][j] *= inv;
    }
    #pragma unroll
    for (int i = 0; i < PP; ++i) {
        float2 o = make_float2(0.f, 0.f);
        #pragma unroll
        for (int j = 0; j < PP; ++j) {
            o.x += dots[i][j] * vv[j].x;
            o.y += dots[i][j] * vv[j].y;
        }
        int n = (b*TT + tt*PP + i)*VV + v;
        *(float2*)(g_ao + (size_t)n*INNER + h*DH + d0) = o;
    }
}

// ---------------- gather for global kv gemm --------------------------------
__global__ void k_gather() {
    int idx = blockIdx.x * 256 + threadIdx.x;       // over 16800*896
    if (idx >= NKTOK*896) return;
    int nk = idx / 896;
    int kkx = idx - nk*896;
    int c  = kkx / PP, kp = kkx - c*PP;
    int v  = nk % VV;
    int rr = nk / VV;
    int tt = rr % NTP;
    int b  = rr / NTP;
    g_xg[idx] = g_xn[((size_t)((b*TT + tt*PP + kp))*VV + v)*CC + c];
}

// ---------------- global attention: one block per (b, h, v) ----------------
__global__ void __launch_bounds__(160) k_gattn() {
    int bid = blockIdx.x;          // 3200
    int v = bid % VV;
    int rr = bid / VV;
    int h = rr & 7;
    int b = rr >> 3;
    __shared__ float ks[NTP][DH];
    __shared__ float vs[NTP][DH];
    for (int idx = threadIdx.x; idx < NTP*DH; idx += 160) {
        int j = idx >> 6, d = idx & 63;
        int nk = (b*NTP + j)*VV + v;
        size_t o = (size_t)nk*(2*INNER) + h*DH + d;
        ks[j][d] = g_kv[o];
        vs[j][d] = g_kv[o + INNER];
    }
    __syncthreads();
    int tid = threadIdx.x;
    if (tid >= 147) return;
    int i0 = 2*tid;                 // rows i0, i0+1  (covers 0..293)
    size_t q0 = (size_t)((b*TT + i0)*VV + v)*INNER + h*DH;
    size_t q1 = q0 + (size_t)VV*INNER;

    float da[NTP], db[NTP];
    #pragma unroll
    for (int j = 0; j < NTP; ++j) { da[j] = 0.f; db[j] = 0.f; }

    for (int dchunk = 0; dchunk < 4; ++dchunk) {
        int dbase = dchunk * 16;
        float qa[16], qb[16];
        #pragma unroll
        for (int dd = 0; dd < 16; dd += 4) {
            *(float4*)&qa[dd] = *(const float4*)(g_q + q0 + dbase + dd);
            *(float4*)&qb[dd] = *(const float4*)(g_q + q1 + dbase + dd);
        }
        #pragma unroll
        for (int j = 0; j < NTP; ++j) {
            #pragma unroll
            for (int dd = 0; dd < 16; ++dd) {
                float kv = ks[j][dbase + dd];
                da[j] += qa[dd] * kv;
                db[j] += qb[dd] * kv;
            }
        }
    }
    // softmax (over 42) for both rows
    {
        float mx = -1e30f;
        #pragma unroll
        for (int j = 0; j < NTP; ++j) { da[j] *= SCALE_ATT; mx = fmaxf(mx, da[j]); }
        float s = 0.f;
        #pragma unroll
        for (int j = 0; j < NTP; ++j) { da[j] = __expf(da[j] - mx); s += da[j]; }
        float inv = 1.f / s;
        #pragma unroll
        for (int j = 0; j < NTP; ++j) da[j] *= inv;
    }
    {
        float mx = -1e30f;
        #pragma unroll
        for (int j = 0; j < NTP; ++j) { db[j] *= SCALE_ATT; mx = fmaxf(mx, db[j]); }
        float s = 0.f;
        #pragma unroll
        for (int j = 0; j < NTP; ++j) { db[j] = __expf(db[j] - mx); s += db[j]; }
        float inv = 1.f / s;
        #pragma unroll
        for (int j = 0; j < NTP; ++j) db[j] *= inv;
    }
    size_t o0 = (size_t)((b*TT + i0)*VV + v)*INNER + h*DH;
    size_t o1 = o0 + (size_t)VV*INNER;
    for (int dchunk = 0; dchunk < 4; ++dchunk) {
        int dbase = dchunk * 16;
        float oa[16], ob[16];
        #pragma unroll
        for (int dd = 0; dd < 16; ++dd) { oa[dd] = 0.f; ob[dd] = 0.f; }
        #pragma unroll
        for (int j = 0; j < NTP; ++j) {
            #pragma unroll
            for (int dd = 0; dd < 16; ++dd) {
                float vv = vs[j][dbase + dd];
                oa[dd] += da[j] * vv;
                ob[dd] += db[j] * vv;
            }
        }
        #pragma unroll
        for (int dd = 0; dd < 16; dd += 4) {
            *(float4*)(g_ao + o0 + dbase + dd) = *(float4*)&oa[dd];
            *(float4*)(g_ao + o1 + dbase + dd) = *(float4*)&ob[dd];
        }
    }
}

// ---------------- launch -----------------------------------------------------
extern "C" void kernel_launch(void* const* d_in, const int* in_sizes, int n_in,
                              void* d_out, int out_size) {
    (void)in_sizes; (void)n_in; (void)out_size;
    float *p_xT, *p_xn, *p_q, *p_kv, *p_ao, *p_xg;
    cudaGetSymbolAddress((void**)&p_xT, g_xT);
    cudaGetSymbolAddress((void**)&p_xn, g_xn);
    cudaGetSymbolAddress((void**)&p_q,  g_q);
    cudaGetSymbolAddress((void**)&p_kv, g_kv);
    cudaGetSymbolAddress((void**)&p_ao, g_ao);
    cudaGetSymbolAddress((void**)&p_xg, g_xg);

    const float* x      = (const float*)d_in[0];
    const float* ln1_g  = (const float*)d_in[1];
    const float* ln1_b  = (const float*)d_in[2];
    const float* la_wq  = (const float*)d_in[3];
    const float* la_wkv = (const float*)d_in[4];
    const float* la_wo  = (const float*)d_in[5];
    const float* la_bo  = (const float*)d_in[6];
    const float* ln2_g  = (const float*)d_in[7];
    const float* ln2_b  = (const float*)d_in[8];
    const float* ff1_w1 = (const float*)d_in[9];
    const float* ff1_b1 = (const float*)d_in[10];
    const float* ff1_w2 = (const float*)d_in[11];
    const float* ff1_b2 = (const float*)d_in[12];
    const float* ln3_g  = (const float*)d_in[13];
    const float* ln3_b  = (const float*)d_in[14];
    const float* ga_wq  = (const float*)d_in[15];
    const float* ga_wkv = (const float*)d_in[16];
    const float* ga_wo  = (const float*)d_in[17];
    const float* ga_bo  = (const float*)d_in[18];
    const float* ln4_g  = (const float*)d_in[19];
    const float* ln4_b  = (const float*)d_in[20];
    const float* ff2_w1 = (const float*)d_in[21];
    const float* ff2_b1 = (const float*)d_in[22];
    const float* ff2_w2 = (const float*)d_in[23];
    const float* ff2_b2 = (const float*)d_in[24];

    const dim3 gQ (8, (NTOK + 63) / 64);    // [N,128]x[128,512]
    const dim3 gKV(16, (NTOK + 63) / 64);   // [N,128]x[128,1024]
    const dim3 gO (2, (NTOK + 63) / 64);    // [N,512]x[512,128]
    const dim3 gGK(16, (NKTOK + 63) / 64);  // [16800,896]x[896,1024]
    const int lnGrid = NTOK / 8;            // 14700

    k_tin<<<BB*TT, 256>>>(x);
    for (int l = 0; l < 2; ++l) {
        // --- local attention block ---
        k_ln<<<lnGrid, 256>>>(ln1_g + l*CC, ln1_b + l*CC);
        k_gemm<0><<<gQ, 256>>>(p_xn, la_wq + (size_t)l*CC*INNER, nullptr, nullptr, p_q, NTOK, CC, INNER);
        k_gemm<0><<<gKV,256>>>(p_xn, la_wkv + (size_t)l*CC*2*INNER, nullptr, nullptr, p_kv, NTOK, CC, 2*INNER);
        k_lattn<<<NKTOK, 256>>>();
        k_gemm<3><<<gO, 256>>>(p_ao, la_wo + (size_t)l*INNER*CC, la_bo + l*CC, p_xT, p_xT, NTOK, INNER, CC);
        // --- ff1 ---
        k_ln<<<lnGrid, 256>>>(ln2_g + l*CC, ln2_b + l*CC);
        k_gemm<2><<<gQ, 256>>>(p_xn, ff1_w1 + (size_t)l*CC*512, ff1_b1 + l*512, nullptr, p_q, NTOK, CC, 512);
        k_gemm<3><<<gO, 256>>>(p_q,  ff1_w2 + (size_t)l*512*CC, ff1_b2 + l*CC, p_xT, p_xT, NTOK, 512, CC);
        // --- global attention block ---
        k_ln<<<lnGrid, 256>>>(ln3_g + l*CC, ln3_b + l*CC);
        k_gemm<0><<<gQ, 256>>>(p_xn, ga_wq + (size_t)l*CC*INNER, nullptr, nullptr, p_q, NTOK, CC, INNER);
        k_gather<<<(NKTOK*896 + 255)/256, 256>>>();
        k_gemm<0><<<gGK,256>>>(p_xg, ga_wkv + (size_t)l*CC*PP*2*INNER, nullptr, nullptr, p_kv, NKTOK, CC*PP, 2*INNER);
        k_gattn<<<BB*NHEAD*VV, 160>>>();
        k_gemm<3><<<gO, 256>>>(p_ao, ga_wo + (size_t)l*INNER*CC, ga_bo + l*CC, p_xT, p_xT, NTOK, INNER, CC);
        // --- ff2 ---
        k_ln<<<lnGrid, 256>>>(ln4_g + l*CC, ln4_b + l*CC);
        k_gemm<2><<<gQ, 256>>>(p_xn, ff2_w1 + (size_t)l*CC*512, ff2_b1 + l*512, nullptr, p_q, NTOK, CC, 512);
        k_gemm<3><<<gO, 256>>>(p_q,  ff2_w2 + (size_t)l*512*CC, ff2_b2 + l*CC, p_xT, p_xT, NTOK, 512, CC);
    }
    k_tout<<<BB*TT, 256>>>((float*)d_out);
}

// round 2
// speedup vs baseline: 1.2925x; 1.2925x over previous
#include <cuda_runtime.h>
#include <math.h>

// ---------------- problem constants ----------------
#define BB     16
#define CC     128
#define TT     294
#define VV     25
#define NTOK   (BB*TT*VV)        // 117600 tokens
#define INNER  512
#define NHEAD  8
#define DH     64
#define PP     7
#define NTP    42                 // T / P
#define NKTOK  (BB*NTP*VV)        // 16800 kv tokens (global)
#define SCALE_ATT 0.125f
#define LN_EPS 1e-5f

// ---------------- scratch (static device memory; no allocs) ----------------
__device__ float g_xT[NTOK*CC];        // residual stream, token-major [N,128]
__device__ float g_xn[NTOK*CC];        // layernorm output
__device__ float g_q [NTOK*INNER];     // q buffer / ff hidden [N,512]
__device__ float g_kv[NTOK*2*INNER];   // local kv [N,1024]; global kv [16800,1024]
__device__ float g_ao[NTOK*INNER];     // attention output [N,512]
__device__ float g_xg[NKTOK*896];      // gathered input for global kv gemm

// ---------------- transpose in: x[B,C,T,V] -> xT[(b t v), c] ----------------
__global__ void k_tin(const float* __restrict__ x) {
    int bt = blockIdx.x;
    int t = bt % TT, b = bt / TT;
    __shared__ float sm[CC*VV];  // sm[c*25+v]
    for (int idx = threadIdx.x; idx < CC*VV; idx += blockDim.x) {
        int c = idx / VV, v = idx % VV;
        sm[idx] = x[(((size_t)b*CC + c)*TT + t)*VV + v];
    }
    __syncthreads();
    size_t base = ((size_t)(b*TT + t))*VV*CC;
    for (int idx = threadIdx.x; idx < CC*VV; idx += blockDim.x) {
        int v = idx / CC, c = idx % CC;   // idx = v*128 + c  (coalesced write)
        g_xT[base + idx] = sm[c*VV + v];
    }
}

// ---------------- transpose out ----------------
__global__ void k_tout(float* __restrict__ out) {
    int bt = blockIdx.x;
    int t = bt % TT, b = bt / TT;
    __shared__ float sm[CC*VV];  // sm[v*128+c]
    size_t base = ((size_t)(b*TT + t))*VV*CC;
    for (int idx = threadIdx.x; idx < CC*VV; idx += blockDim.x)
        sm[idx] = g_xT[base + idx];
    __syncthreads();
    for (int idx = threadIdx.x; idx < CC*VV; idx += blockDim.x) {
        int c = idx / VV, v = idx % VV;
        out[(((size_t)b*CC + c)*TT + t)*VV + v] = sm[v*CC + c];
    }
}

// ---------------- channel layernorm: one warp per token ----------------
__global__ void __launch_bounds__(256) k_ln(const float* __restrict__ gam,
                                            const float* __restrict__ bet) {
    int n = blockIdx.x * 8 + (threadIdx.x >> 5);
    if (n >= NTOK) return;
    int lane = threadIdx.x & 31;
    float4 a = ((const float4*)(g_xT + (size_t)n*CC))[lane];
    float s  = a.x + a.y + a.z + a.w;
    float ss = a.x*a.x + a.y*a.y + a.z*a.z + a.w*a.w;
    #pragma unroll
    for (int o = 16; o; o >>= 1) {
        s  += __shfl_xor_sync(0xffffffffu, s,  o);
        ss += __shfl_xor_sync(0xffffffffu, ss, o);
    }
    float m   = s * (1.f/128.f);
    float var = ss * (1.f/128.f) - m*m;
    float r   = rsqrtf(var + LN_EPS);
    float4 gg = ((const float4*)gam)[lane];
    float4 bb = ((const float4*)bet)[lane];
    float4 o4;
    o4.x = (a.x - m)*r*gg.x + bb.x;
    o4.y = (a.y - m)*r*gg.y + bb.y;
    o4.z = (a.z - m)*r*gg.z + bb.z;
    o4.w = (a.w - m)*r*gg.w + bb.w;
    ((float4*)(g_xn + (size_t)n*CC))[lane] = o4;
}

// ---------------- SGEMM: C[N,M] = A[N,K] @ W[K,M] (+epilogue) ---------------
// 128x128 tile, K-tile 8, double-buffered smem, 8x8 per thread.
// EPI: 0 = none, 2 = bias+gelu(exact), 3 = bias+residual
__device__ __forceinline__ float gelu_exact(float v) {
    return 0.5f * v * (1.0f + erff(v * 0.7071067811865475f));
}

template<int EPI>
__global__ void __launch_bounds__(256) k_gemm(
    const float* __restrict__ A, const float* __restrict__ W,
    const float* __restrict__ bias, const float* __restrict__ res,
    float* __restrict__ C, int Nrows, int K, int M)
{
    __shared__ float As[2][8][128];
    __shared__ float Bs[2][8][128];

    const int tid = threadIdx.x;
    const int rowBase = blockIdx.y << 7;
    const int colBase = blockIdx.x << 7;
    const int tx = tid & 15;          // 0..15 -> col groups
    const int ty = tid >> 4;          // 0..15 -> row groups

    // global-load assignments
    const int aRow = tid >> 1;            // 0..127
    const int aK   = (tid & 1) << 2;      // 0 or 4
    const int bK   = tid >> 5;            // 0..7
    const int bM   = (tid & 31) << 2;     // 0..124

    int aRowG = rowBase + aRow;
    if (aRowG >= Nrows) aRowG = Nrows - 1;      // clamp (garbage discarded at store)
    const float* Aptr = A + (size_t)aRowG * K + aK;
    const float* Wptr = W + (size_t)bK * M + colBase + bM;

    const int nk = K >> 3;
    float acc[8][8];
    #pragma unroll
    for (int i = 0; i < 8; ++i)
        #pragma unroll
        for (int j = 0; j < 8; ++j) acc[i][j] = 0.f;

    // prologue: load tile 0
    {
        float4 av = *(const float4*)(Aptr);
        float4 bv = *(const float4*)(Wptr);
        As[0][aK+0][aRow] = av.x; As[0][aK+1][aRow] = av.y;
        As[0][aK+2][aRow] = av.z; As[0][aK+3][aRow] = av.w;
        *(float4*)&Bs[0][bK][bM] = bv;
    }
    __syncthreads();

    int buf = 0;
    for (int kt = 0; kt < nk; ++kt) {
        float4 av, bv;
        const bool more = (kt + 1 < nk);
        if (more) {
            av = *(const float4*)(Aptr + ((kt+1) << 3));
            bv = *(const float4*)(Wptr + (size_t)((kt+1) << 3) * M);
        }
        #pragma unroll
        for (int k = 0; k < 8; ++k) {
            float4 a0 = *(const float4*)&As[buf][k][ty << 2];
            float4 a1 = *(const float4*)&As[buf][k][64 + (ty << 2)];
            float4 b0 = *(const float4*)&Bs[buf][k][tx << 2];
            float4 b1 = *(const float4*)&Bs[buf][k][64 + (tx << 2)];
            float ar[8] = {a0.x, a0.y, a0.z, a0.w, a1.x, a1.y, a1.z, a1.w};
            float br[8] = {b0.x, b0.y, b0.z, b0.w, b1.x, b1.y, b1.z, b1.w};
            #pragma unroll
            for (int i = 0; i < 8; ++i)
                #pragma unroll
                for (int j = 0; j < 8; ++j)
                    acc[i][j] += ar[i] * br[j];
        }
        if (more) {
            int nb = buf ^ 1;
            As[nb][aK+0][aRow] = av.x; As[nb][aK+1][aRow] = av.y;
            As[nb][aK+2][aRow] = av.z; As[nb][aK+3][aRow] = av.w;
            *(float4*)&Bs[nb][bK][bM] = bv;
        }
        __syncthreads();
        buf ^= 1;
    }

    // epilogue
    const int col0 = colBase + (tx << 2);
    float4 bv0 = make_float4(0.f,0.f,0.f,0.f), bv1 = bv0;
    if (EPI >= 1) {
        bv0 = *(const float4*)(bias + col0);
        bv1 = *(const float4*)(bias + col0 + 64);
    }
    #pragma unroll
    for (int half = 0; half < 2; ++half) {
        #pragma unroll
        for (int i = 0; i < 4; ++i) {
            int r = rowBase + half*64 + (ty << 2) + i;
            if (r >= Nrows) continue;
            int ii = half*4 + i;
            float4 o0, o1;
            o0.x = acc[ii][0] + bv0.x; o0.y = acc[ii][1] + bv0.y;
            o0.z = acc[ii][2] + bv0.z; o0.w = acc[ii][3] + bv0.w;
            o1.x = acc[ii][4] + bv1.x; o1.y = acc[ii][5] + bv1.y;
            o1.z = acc[ii][6] + bv1.z; o1.w = acc[ii][7] + bv1.w;
            if (EPI == 2) {
                o0.x = gelu_exact(o0.x); o0.y = gelu_exact(o0.y);
                o0.z = gelu_exact(o0.z); o0.w = gelu_exact(o0.w);
                o1.x = gelu_exact(o1.x); o1.y = gelu_exact(o1.y);
                o1.z = gelu_exact(o1.z); o1.w = gelu_exact(o1.w);
            }
            if (EPI == 3) {
                float4 r0 = *(const float4*)(res + (size_t)r*M + col0);
                float4 r1 = *(const float4*)(res + (size_t)r*M + col0 + 64);
                o0.x += r0.x; o0.y += r0.y; o0.z += r0.z; o0.w += r0.w;
                o1.x += r1.x; o1.y += r1.y; o1.z += r1.z; o1.w += r1.w;
            }
            *(float4*)(C + (size_t)r*M + col0)      = o0;
            *(float4*)(C + (size_t)r*M + col0 + 64) = o1;
        }
    }
}

// ---------------- local attention: one warp per (b, patch, v, head) --------
__global__ void __launch_bounds__(256) k_lattn() {
    int w = blockIdx.x * 8 + (threadIdx.x >> 5);   // 0 .. 134399
    int lane = threadIdx.x & 31;
    int h = w & 7;
    int g = w >> 3;                // (b, tt, v)
    int v = g % VV;
    int r = g / VV;
    int tt = r % NTP;
    int b = r / NTP;
    int d0 = lane * 2;

    float2 q[PP], kk[PP], vv[PP];
    #pragma unroll
    for (int p = 0; p < PP; ++p) {
        int n = (b*TT + tt*PP + p)*VV + v;
        q[p]  = *(const float2*)(g_q  + (size_t)n*INNER + h*DH + d0);
        size_t ko = (size_t)n*(2*INNER) + h*DH + d0;
        kk[p] = *(const float2*)(g_kv + ko);
        vv[p] = *(const float2*)(g_kv + ko + INNER);
    }
    float dots[PP][PP];
    #pragma unroll
    for (int i = 0; i < PP; ++i)
        #pragma unroll
        for (int j = 0; j < PP; ++j)
            dots[i][j] = q[i].x*kk[j].x + q[i].y*kk[j].y;
    #pragma unroll
    for (int o = 16; o; o >>= 1)
        #pragma unroll
        for (int i = 0; i < PP; ++i)
            #pragma unroll
            for (int j = 0; j < PP; ++j)
                dots[i][j] += __shfl_xor_sync(0xffffffffu, dots[i][j], o);
    #pragma unroll
    for (int i = 0; i < PP; ++i) {
        float mx = -1e30f;
        #pragma unroll
        for (int j = 0; j < PP; ++j) {
            dots[i][j] *= SCALE_ATT;
            mx = fmaxf(mx, dots[i][j]);
        }
        float s = 0.f;
        #pragma unroll
        for (int j = 0; j < PP; ++j) { dots[i][j] = __expf(dots[i][j] - mx); s += dots[i][j]; }
        float inv = 1.f / s;
        #pragma unroll
        for (int j = 0; j < PP; ++j) dots[i][j] *= inv;
    }
    #pragma unroll
    for (int i = 0; i < PP; ++i) {
        float2 o = make_float2(0.f, 0.f);
        #pragma unroll
        for (int j = 0; j < PP; ++j) {
            o.x += dots[i][j] * vv[j].x;
            o.y += dots[i][j] * vv[j].y;
        }
        int n = (b*TT + tt*PP + i)*VV + v;
        *(float2*)(g_ao + (size_t)n*INNER + h*DH + d0) = o;
    }
}

// ---------------- gather for global kv gemm --------------------------------
__global__ void k_gather() {
    int idx = blockIdx.x * 256 + threadIdx.x;       // over 16800*896
    if (idx >= NKTOK*896) return;
    int nk = idx / 896;
    int kkx = idx - nk*896;
    int c  = kkx / PP, kp = kkx - c*PP;
    int v  = nk % VV;
    int rr = nk / VV;
    int tt = rr % NTP;
    int b  = rr / NTP;
    g_xg[idx] = g_xn[((size_t)((b*TT + tt*PP + kp))*VV + v)*CC + c];
}

// ---------------- global attention: one block per (b, h, v) ----------------
__global__ void __launch_bounds__(160) k_gattn() {
    int bid = blockIdx.x;          // 3200
    int v = bid % VV;
    int rr = bid / VV;
    int h = rr & 7;
    int b = rr >> 3;
    __shared__ float ks[NTP][DH];
    __shared__ float vs[NTP][DH];
    for (int idx = threadIdx.x; idx < NTP*DH; idx += 160) {
        int j = idx >> 6, d = idx & 63;
        int nk = (b*NTP + j)*VV + v;
        size_t o = (size_t)nk*(2*INNER) + h*DH + d;
        ks[j][d] = g_kv[o];
        vs[j][d] = g_kv[o + INNER];
    }
    __syncthreads();
    int tid = threadIdx.x;
    if (tid >= 147) return;
    int i0 = 2*tid;
    size_t q0 = (size_t)((b*TT + i0)*VV + v)*INNER + h*DH;
    size_t q1 = q0 + (size_t)VV*INNER;

    float da[NTP], db[NTP];
    #pragma unroll
    for (int j = 0; j < NTP; ++j) { da[j] = 0.f; db[j] = 0.f; }

    for (int dchunk = 0; dchunk < 4; ++dchunk) {
        int dbase = dchunk * 16;
        float qa[16], qb[16];
        #pragma unroll
        for (int dd = 0; dd < 16; dd += 4) {
            *(float4*)&qa[dd] = *(const float4*)(g_q + q0 + dbase + dd);
            *(float4*)&qb[dd] = *(const float4*)(g_q + q1 + dbase + dd);
        }
        #pragma unroll
        for (int j = 0; j < NTP; ++j) {
            #pragma unroll
            for (int dd = 0; dd < 16; ++dd) {
                float kv = ks[j][dbase + dd];
                da[j] += qa[dd] * kv;
                db[j] += qb[dd] * kv;
            }
        }
    }
    {
        float mx = -1e30f;
        #pragma unroll
        for (int j = 0; j < NTP; ++j) { da[j] *= SCALE_ATT; mx = fmaxf(mx, da[j]); }
        float s = 0.f;
        #pragma unroll
        for (int j = 0; j < NTP; ++j) { da[j] = __expf(da[j] - mx); s += da[j]; }
        float inv = 1.f / s;
        #pragma unroll
        for (int j = 0; j < NTP; ++j) da[j] *= inv;
    }
    {
        float mx = -1e30f;
        #pragma unroll
        for (int j = 0; j < NTP; ++j) { db[j] *= SCALE_ATT; mx = fmaxf(mx, db[j]); }
        float s = 0.f;
        #pragma unroll
        for (int j = 0; j < NTP; ++j) { db[j] = __expf(db[j] - mx); s += db[j]; }
        float inv = 1.f / s;
        #pragma unroll
        for (int j = 0; j < NTP; ++j) db[j] *= inv;
    }
    size_t o0 = (size_t)((b*TT + i0)*VV + v)*INNER + h*DH;
    size_t o1 = o0 + (size_t)VV*INNER;
    for (int dchunk = 0; dchunk < 4; ++dchunk) {
        int dbase = dchunk * 16;
        float oa[16], ob[16];
        #pragma unroll
        for (int dd = 0; dd < 16; ++dd) { oa[dd] = 0.f; ob[dd] = 0.f; }
        #pragma unroll
        for (int j = 0; j < NTP; ++j) {
            #pragma unroll
            for (int dd = 0; dd < 16; ++dd) {
                float vv = vs[j][dbase + dd];
                oa[dd] += da[j] * vv;
                ob[dd] += db[j] * vv;
            }
        }
        #pragma unroll
        for (int dd = 0; dd < 16; dd += 4) {
            *(float4*)(g_ao + o0 + dbase + dd) = *(float4*)&oa[dd];
            *(float4*)(g_ao + o1 + dbase + dd) = *(float4*)&ob[dd];
        }
    }
}

// ---------------- launch -----------------------------------------------------
extern "C" void kernel_launch(void* const* d_in, const int* in_sizes, int n_in,
                              void* d_out, int out_size) {
    (void)in_sizes; (void)n_in; (void)out_size;
    float *p_xT, *p_xn, *p_q, *p_kv, *p_ao, *p_xg;
    cudaGetSymbolAddress((void**)&p_xT, g_xT);
    cudaGetSymbolAddress((void**)&p_xn, g_xn);
    cudaGetSymbolAddress((void**)&p_q,  g_q);
    cudaGetSymbolAddress((void**)&p_kv, g_kv);
    cudaGetSymbolAddress((void**)&p_ao, g_ao);
    cudaGetSymbolAddress((void**)&p_xg, g_xg);

    const float* x      = (const float*)d_in[0];
    const float* ln1_g  = (const float*)d_in[1];
    const float* ln1_b  = (const float*)d_in[2];
    const float* la_wq  = (const float*)d_in[3];
    const float* la_wkv = (const float*)d_in[4];
    const float* la_wo  = (const float*)d_in[5];
    const float* la_bo  = (const float*)d_in[6];
    const float* ln2_g  = (const float*)d_in[7];
    const float* ln2_b  = (const float*)d_in[8];
    const float* ff1_w1 = (const float*)d_in[9];
    const float* ff1_b1 = (const float*)d_in[10];
    const float* ff1_w2 = (const float*)d_in[11];
    const float* ff1_b2 = (const float*)d_in[12];
    const float* ln3_g  = (const float*)d_in[13];
    const float* ln3_b  = (const float*)d_in[14];
    const float* ga_wq  = (const float*)d_in[15];
    const float* ga_wkv = (const float*)d_in[16];
    const float* ga_wo  = (const float*)d_in[17];
    const float* ga_bo  = (const float*)d_in[18];
    const float* ln4_g  = (const float*)d_in[19];
    const float* ln4_b  = (const float*)d_in[20];
    const float* ff2_w1 = (const float*)d_in[21];
    const float* ff2_b1 = (const float*)d_in[22];
    const float* ff2_w2 = (const float*)d_in[23];
    const float* ff2_b2 = (const float*)d_in[24];

    const int rowTiles  = (NTOK  + 127) / 128;   // 919
    const int rowTilesG = (NKTOK + 127) / 128;   // 132
    const dim3 gQ (4,  rowTiles);    // [N,128]x[128,512]
    const dim3 gKV(8,  rowTiles);    // [N,128]x[128,1024]
    const dim3 gO (1,  rowTiles);    // [N,512]x[512,128]
    const dim3 gGK(8,  rowTilesG);   // [16800,896]x[896,1024]
    const int lnGrid = NTOK / 8;     // 14700

    k_tin<<<BB*TT, 256>>>(x);
    for (int l = 0; l < 2; ++l) {
        // --- local attention block ---
        k_ln<<<lnGrid, 256>>>(ln1_g + l*CC, ln1_b + l*CC);
        k_gemm<0><<<gQ, 256>>>(p_xn, la_wq + (size_t)l*CC*INNER, nullptr, nullptr, p_q, NTOK, CC, INNER);
        k_gemm<0><<<gKV,256>>>(p_xn, la_wkv + (size_t)l*CC*2*INNER, nullptr, nullptr, p_kv, NTOK, CC, 2*INNER);
        k_lattn<<<NKTOK, 256>>>();
        k_gemm<3><<<gO, 256>>>(p_ao, la_wo + (size_t)l*INNER*CC, la_bo + l*CC, p_xT, p_xT, NTOK, INNER, CC);
        // --- ff1 ---
        k_ln<<<lnGrid, 256>>>(ln2_g + l*CC, ln2_b + l*CC);
        k_gemm<2><<<gQ, 256>>>(p_xn, ff1_w1 + (size_t)l*CC*512, ff1_b1 + l*512, nullptr, p_q, NTOK, CC, 512);
        k_gemm<3><<<gO, 256>>>(p_q,  ff1_w2 + (size_t)l*512*CC, ff1_b2 + l*CC, p_xT, p_xT, NTOK, 512, CC);
        // --- global attention block ---
        k_ln<<<lnGrid, 256>>>(ln3_g + l*CC, ln3_b + l*CC);
        k_gemm<0><<<gQ, 256>>>(p_xn, ga_wq + (size_t)l*CC*INNER, nullptr, nullptr, p_q, NTOK, CC, INNER);
        k_gather<<<(NKTOK*896 + 255)/256, 256>>>();
        k_gemm<0><<<gGK,256>>>(p_xg, ga_wkv + (size_t)l*CC*PP*2*INNER, nullptr, nullptr, p_kv, NKTOK, CC*PP, 2*INNER);
        k_gattn<<<BB*NHEAD*VV, 160>>>();
        k_gemm<3><<<gO, 256>>>(p_ao, ga_wo + (size_t)l*INNER*CC, ga_bo + l*CC, p_xT, p_xT, NTOK, INNER, CC);
        // --- ff2 ---
        k_ln<<<lnGrid, 256>>>(ln4_g + l*CC, ln4_b + l*CC);
        k_gemm<2><<<gQ, 256>>>(p_xn, ff2_w1 + (size_t)l*CC*512, ff2_b1 + l*512, nullptr, p_q, NTOK, CC, 512);
        k_gemm<3><<<gO, 256>>>(p_q,  ff2_w2 + (size_t)l*512*CC, ff2_b2 + l*CC, p_xT, p_xT, NTOK, 512, CC);
    }
    k_tout<<<BB*TT, 256>>>((float*)d_out);
}

// round 4
// speedup vs baseline: 1.7821x; 1.3788x over previous
#include <cuda_runtime.h>
#include <math.h>
#include <stdint.h>

// ---------------- problem constants ----------------
#define BB     16
#define CC     128
#define TT     294
#define VV     25
#define NTOK   (BB*TT*VV)        // 117600 tokens
#define INNER  512
#define NHEAD  8
#define DH     64
#define PP     7
#define NTP    42                 // T / P
#define NKTOK  (BB*NTP*VV)        // 16800 kv tokens (global)
#define SCALE_ATT 0.125f
#define LN_EPS 1e-5f

// transposed-weight scratch layout (floats, per layer)
#define OFF_WQ    0
#define OFF_WKV   65536
#define OFF_WO    196608
#define OFF_F1A   262144
#define OFF_F1B   327680
#define OFF_GWQ   393216
#define OFF_GWKV  458752
#define OFF_GWO   1376256
#define OFF_F2A   1441792
#define OFF_F2B   1507328
#define WT_LSZ    1572864

// ---------------- scratch (static device memory; no allocs) ----------------
__device__ float g_xT[NTOK*CC];
__device__ float g_xn[NTOK*CC];
__device__ float g_q [NTOK*INNER];
__device__ float g_kv[NTOK*2*INNER];
__device__ float g_ao[NTOK*INNER];
__device__ float g_xg[NKTOK*896];
__device__ float g_wt[2*WT_LSZ];       // tf32-rounded transposed weights

// ---------------- helpers ----------------
__device__ __forceinline__ uint4 cvt4_tf32(float4 v) {
    uint4 o;
    asm("cvt.rna.tf32.f32 %0, %1;" : "=r"(o.x) : "f"(v.x));
    asm("cvt.rna.tf32.f32 %0, %1;" : "=r"(o.y) : "f"(v.y));
    asm("cvt.rna.tf32.f32 %0, %1;" : "=r"(o.z) : "f"(v.z));
    asm("cvt.rna.tf32.f32 %0, %1;" : "=r"(o.w) : "f"(v.w));
    return o;
}
__device__ __forceinline__ void mma_tf32(float* d, const uint32_t* a, const uint32_t* b) {
    asm volatile(
        "mma.sync.aligned.m16n8k8.row.col.f32.tf32.tf32.f32 "
        "{%0,%1,%2,%3}, {%4,%5,%6,%7}, {%8,%9}, {%0,%1,%2,%3};"
        : "+f"(d[0]), "+f"(d[1]), "+f"(d[2]), "+f"(d[3])
        : "r"(a[0]), "r"(a[1]), "r"(a[2]), "r"(a[3]), "r"(b[0]), "r"(b[1]));
}
__device__ __forceinline__ float gelu_exact(float v) {
    return 0.5f * v * (1.0f + erff(v * 0.7071067811865475f));
}

// ---------------- transpose in: x[B,C,T,V] -> xT[(b t v), c] ----------------
__global__ void k_tin(const float* __restrict__ x) {
    int bt = blockIdx.x;
    int t = bt % TT, b = bt / TT;
    __shared__ float sm[CC*VV];
    for (int idx = threadIdx.x; idx < CC*VV; idx += blockDim.x) {
        int c = idx / VV, v = idx % VV;
        sm[idx] = x[(((size_t)b*CC + c)*TT + t)*VV + v];
    }
    __syncthreads();
    size_t base = ((size_t)(b*TT + t))*VV*CC;
    for (int idx = threadIdx.x; idx < CC*VV; idx += blockDim.x) {
        int v = idx / CC, c = idx % CC;
        g_xT[base + idx] = sm[c*VV + v];
    }
}

__global__ void k_tout(float* __restrict__ out) {
    int bt = blockIdx.x;
    int t = bt % TT, b = bt / TT;
    __shared__ float sm[CC*VV];
    size_t base = ((size_t)(b*TT + t))*VV*CC;
    for (int idx = threadIdx.x; idx < CC*VV; idx += blockDim.x)
        sm[idx] = g_xT[base + idx];
    __syncthreads();
    for (int idx = threadIdx.x; idx < CC*VV; idx += blockDim.x) {
        int c = idx / VV, v = idx % VV;
        out[(((size_t)b*CC + c)*TT + t)*VV + v] = sm[v*CC + c];
    }
}

// ---------------- weight transpose + tf32 rounding: Wt[M,K] = W[K,M] -------
__global__ void k_wt(const float* __restrict__ W, float* __restrict__ Wt, int K, int M) {
    int idx = blockIdx.x * 256 + threadIdx.x;
    if (idx >= K*M) return;
    int m = idx / K, k = idx - m*K;
    float v = W[(size_t)k*M + m];
    uint32_t o;
    asm("cvt.rna.tf32.f32 %0, %1;" : "=r"(o) : "f"(v));
    Wt[idx] = __uint_as_float(o);
}

// ---------------- channel layernorm ----------------
__global__ void __launch_bounds__(256) k_ln(const float* __restrict__ gam,
                                            const float* __restrict__ bet) {
    int n = blockIdx.x * 8 + (threadIdx.x >> 5);
    if (n >= NTOK) return;
    int lane = threadIdx.x & 31;
    float4 a = ((const float4*)(g_xT + (size_t)n*CC))[lane];
    float s  = a.x + a.y + a.z + a.w;
    float ss = a.x*a.x + a.y*a.y + a.z*a.z + a.w*a.w;
    #pragma unroll
    for (int o = 16; o; o >>= 1) {
        s  += __shfl_xor_sync(0xffffffffu, s,  o);
        ss += __shfl_xor_sync(0xffffffffu, ss, o);
    }
    float m   = s * (1.f/128.f);
    float var = ss * (1.f/128.f) - m*m;
    float r   = rsqrtf(var + LN_EPS);
    float4 gg = ((const float4*)gam)[lane];
    float4 bb = ((const float4*)bet)[lane];
    float4 o4;
    o4.x = (a.x - m)*r*gg.x + bb.x;
    o4.y = (a.y - m)*r*gg.y + bb.y;
    o4.z = (a.z - m)*r*gg.z + bb.z;
    o4.w = (a.w - m)*r*gg.w + bb.w;
    ((float4*)(g_xn + (size_t)n*CC))[lane] = o4;
}

// ---------------- tf32 mma.sync GEMM: C[N,M] = A[N,K] @ Wt[M,K]^T ----------
// 128x128 CTA tile, K-tile 32, 2-stage smem, fragment-permuted smem layout.
// 8 warps: warpRow = wid&1 (64 rows), warpCol = wid>>1 (32 cols).
// EPI: 0 none, 2 bias+gelu, 3 bias+residual
#define GEMM_SMEM 65536

template<int EPI>
__global__ void __launch_bounds__(256) k_gemm_mma(
    const float* __restrict__ A, const float* __restrict__ Wt,
    const float* __restrict__ bias, const float* __restrict__ res,
    float* __restrict__ C, int Nrows, int K, int M)
{
    extern __shared__ float sm[];   // [2 stages][A:4096 | B:4096]

    const int t = threadIdx.x;
    const int lane = t & 31;
    const int wid = t >> 5;
    const int wr = wid & 1;
    const int wc = wid >> 1;
    const int rowBase = blockIdx.y << 7;
    const int colBase = blockIdx.x << 7;

    // staging assignment: thread loads 4 float4 of A and 4 of B per k-tile
    const int rL = t >> 3;           // 0..31
    const int c0 = (t & 7) << 2;     // 0,4,...,28
    const int ksS   = c0 >> 3;       // kstep 0..3
    const int chalf = (c0 >> 2) & 1; // k half within kstep

    int aIdx[4], bIdx[4];
    const float* aPtr[4];
    const float* bPtr[4];
    #pragma unroll
    for (int i = 0; i < 4; ++i) {
        const int r = rL + (i << 5);              // 0..127
        aIdx[i] = ((((r >> 4) * 4 + ksS) * 32 + ((r & 7) << 2)) << 2)
                  + (chalf << 1) + ((r >> 3) & 1);
        int ga = rowBase + r; if (ga >= Nrows) ga = Nrows - 1;
        aPtr[i] = A + (size_t)ga * K + c0;
        bIdx[i] = ((((r >> 3) * 4 + ksS) * 32 + ((r & 7) << 2)) << 1) + chalf;
        bPtr[i] = Wt + (size_t)(colBase + r) * K + c0;
    }

    float acc[4][4][4];
    #pragma unroll
    for (int mt = 0; mt < 4; ++mt)
        #pragma unroll
        for (int nt = 0; nt < 4; ++nt)
            #pragma unroll
            for (int e = 0; e < 4; ++e) acc[mt][nt][e] = 0.f;

    const int nk = K >> 5;

    float4 av[4], bv[4];
    #pragma unroll
    for (int i = 0; i < 4; ++i) { av[i] = *(const float4*)aPtr[i]; bv[i] = *(const float4*)bPtr[i]; }
    {   // STS stage 0
        float* Asm = sm;
        float* Bsm = sm + 4096;
        #pragma unroll
        for (int i = 0; i < 4; ++i) {
            uint4 ac = cvt4_tf32(av[i]);
            Asm[aIdx[i]+0]  = __uint_as_float(ac.x);
            Asm[aIdx[i]+4]  = __uint_as_float(ac.y);
            Asm[aIdx[i]+8]  = __uint_as_float(ac.z);
            Asm[aIdx[i]+12] = __uint_as_float(ac.w);
            Bsm[bIdx[i]+0] = bv[i].x;
            Bsm[bIdx[i]+2] = bv[i].y;
            Bsm[bIdx[i]+4] = bv[i].z;
            Bsm[bIdx[i]+6] = bv[i].w;
        }
    }
    __syncthreads();

    for (int kt = 0; kt < nk; ++kt) {
        const int s = kt & 1;
        const bool more = (kt + 1 < nk);
        if (more) {
            const int ko = (kt + 1) << 5;
            #pragma unroll
            for (int i = 0; i < 4; ++i) {
                av[i] = *(const float4*)(aPtr[i] + ko);
                bv[i] = *(const float4*)(bPtr[i] + ko);
            }
        }
        // compute stage s
        {
            const float* Asm = sm + s*8192;
            const float* Bsm = Asm + 4096;
            #pragma unroll
            for (int ks = 0; ks < 4; ++ks) {
                uint32_t afr[4][4];
                uint32_t bfr[4][2];
                #pragma unroll
                for (int mt = 0; mt < 4; ++mt)
                    *(uint4*)afr[mt] = *(const uint4*)&Asm[((((wr*4+mt)*4 + ks)*32 + lane) << 2)];
                #pragma unroll
                for (int nt = 0; nt < 4; ++nt)
                    *(uint2*)bfr[nt] = *(const uint2*)&Bsm[((((wc*4+nt)*4 + ks)*32 + lane) << 1)];
                #pragma unroll
                for (int mt = 0; mt < 4; ++mt)
                    #pragma unroll
                    for (int nt = 0; nt < 4; ++nt)
                        mma_tf32(acc[mt][nt], afr[mt], bfr[nt]);
            }
        }
        if (more) {
            float* Asm = sm + (s^1)*8192;
            float* Bsm = Asm + 4096;
            #pragma unroll
            for (int i = 0; i < 4; ++i) {
                uint4 ac = cvt4_tf32(av[i]);
                Asm[aIdx[i]+0]  = __uint_as_float(ac.x);
                Asm[aIdx[i]+4]  = __uint_as_float(ac.y);
                Asm[aIdx[i]+8]  = __uint_as_float(ac.z);
                Asm[aIdx[i]+12] = __uint_as_float(ac.w);
                Bsm[bIdx[i]+0] = bv[i].x;
                Bsm[bIdx[i]+2] = bv[i].y;
                Bsm[bIdx[i]+4] = bv[i].z;
                Bsm[bIdx[i]+6] = bv[i].w;
            }
        }
        __syncthreads();
    }

    // ---------------- epilogue ----------------
    #pragma unroll
    for (int nt = 0; nt < 4; ++nt) {
        const int col = colBase + wc*32 + nt*8 + (lane & 3)*2;
        float2 bb = make_float2(0.f, 0.f);
        if (EPI >= 1) bb = *(const float2*)(bias + col);
        #pragma unroll
        for (int mt = 0; mt < 4; ++mt) {
            const int row0 = rowBase + wr*64 + mt*16 + (lane >> 2);
            #pragma unroll
            for (int half = 0; half < 2; ++half) {
                const int r = row0 + half*8;
                if (r >= Nrows) continue;
                float2 o = make_float2(acc[mt][nt][half*2+0] + bb.x,
                                       acc[mt][nt][half*2+1] + bb.y);
                if (EPI == 2) { o.x = gelu_exact(o.x); o.y = gelu_exact(o.y); }
                if (EPI == 3) {
                    float2 rv = *(const float2*)(res + (size_t)r*M + col);
                    o.x += rv.x; o.y += rv.y;
                }
                *(float2*)(C + (size_t)r*M + col) = o;
            }
        }
    }
}

// ---------------- local attention: one warp per (b, patch, v, head) --------
__global__ void __launch_bounds__(256) k_lattn() {
    int w = blockIdx.x * 8 + (threadIdx.x >> 5);
    int lane = threadIdx.x & 31;
    int h = w & 7;
    int g = w >> 3;
    int v = g % VV;
    int r = g / VV;
    int tt = r % NTP;
    int b = r / NTP;
    int d0 = lane * 2;

    float2 q[PP], kk[PP], vv[PP];
    #pragma unroll
    for (int p = 0; p < PP; ++p) {
        int n = (b*TT + tt*PP + p)*VV + v;
        q[p]  = *(const float2*)(g_q  + (size_t)n*INNER + h*DH + d0);
        size_t ko = (size_t)n*(2*INNER) + h*DH + d0;
        kk[p] = *(const float2*)(g_kv + ko);
        vv[p] = *(const float2*)(g_kv + ko + INNER);
    }
    float dots[PP][PP];
    #pragma unroll
    for (int i = 0; i < PP; ++i)
        #pragma unroll
        for (int j = 0; j < PP; ++j)
            dots[i][j] = q[i].x*kk[j].x + q[i].y*kk[j].y;
    #pragma unroll
    for (int o = 16; o; o >>= 1)
        #pragma unroll
        for (int i = 0; i < PP; ++i)
            #pragma unroll
            for (int j = 0; j < PP; ++j)
                dots[i][j] += __shfl_xor_sync(0xffffffffu, dots[i][j], o);
    #pragma unroll
    for (int i = 0; i < PP; ++i) {
        float mx = -1e30f;
        #pragma unroll
        for (int j = 0; j < PP; ++j) {
            dots[i][j] *= SCALE_ATT;
            mx = fmaxf(mx, dots[i][j]);
        }
        float s = 0.f;
        #pragma unroll
        for (int j = 0; j < PP; ++j) { dots[i][j] = __expf(dots[i][j] - mx); s += dots[i][j]; }
        float inv = 1.f / s;
        #pragma unroll
        for (int j = 0; j < PP; ++j) dots[i][j] *= inv;
    }
    #pragma unroll
    for (int i = 0; i < PP; ++i) {
        float2 o = make_float2(0.f, 0.f);
        #pragma unroll
        for (int j = 0; j < PP; ++j) {
            o.x += dots[i][j] * vv[j].x;
            o.y += dots[i][j] * vv[j].y;
        }
        int n = (b*TT + tt*PP + i)*VV + v;
        *(float2*)(g_ao + (size_t)n*INNER + h*DH + d0) = o;
    }
}

// ---------------- gather for global kv gemm --------------------------------
__global__ void k_gather() {
    int idx = blockIdx.x * 256 + threadIdx.x;
    if (idx >= NKTOK*896) return;
    int nk = idx / 896;
    int kkx = idx - nk*896;
    int c  = kkx / PP, kp = kkx - c*PP;
    int v  = nk % VV;
    int rr = nk / VV;
    int tt = rr % NTP;
    int b  = rr / NTP;
    g_xg[idx] = g_xn[((size_t)((b*TT + tt*PP + kp))*VV + v)*CC + c];
}

// ---------------- global attention: one block per (b, h, v) ----------------
__global__ void __launch_bounds__(160) k_gattn() {
    int bid = blockIdx.x;
    int v = bid % VV;
    int rr = bid / VV;
    int h = rr & 7;
    int b = rr >> 3;
    __shared__ float ks[NTP][DH];
    __shared__ float vs[NTP][DH];
    for (int idx = threadIdx.x; idx < NTP*DH; idx += 160) {
        int j = idx >> 6, d = idx & 63;
        int nk = (b*NTP + j)*VV + v;
        size_t o = (size_t)nk*(2*INNER) + h*DH + d;
        ks[j][d] = g_kv[o];
        vs[j][d] = g_kv[o + INNER];
    }
    __syncthreads();
    int tid = threadIdx.x;
    if (tid >= 147) return;
    int i0 = 2*tid;
    size_t q0 = (size_t)((b*TT + i0)*VV + v)*INNER + h*DH;
    size_t q1 = q0 + (size_t)VV*INNER;

    float da[NTP], db[NTP];
    #pragma unroll
    for (int j = 0; j < NTP; ++j) { da[j] = 0.f; db[j] = 0.f; }

    for (int dchunk = 0; dchunk < 4; ++dchunk) {
        int dbase = dchunk * 16;
        float qa[16], qb[16];
        #pragma unroll
        for (int dd = 0; dd < 16; dd += 4) {
            *(float4*)&qa[dd] = *(const float4*)(g_q + q0 + dbase + dd);
            *(float4*)&qb[dd] = *(const float4*)(g_q + q1 + dbase + dd);
        }
        #pragma unroll
        for (int j = 0; j < NTP; ++j) {
            #pragma unroll
            for (int dd = 0; dd < 16; ++dd) {
                float kv = ks[j][dbase + dd];
                da[j] += qa[dd] * kv;
                db[j] += qb[dd] * kv;
            }
        }
    }
    {
        float mx = -1e30f;
        #pragma unroll
        for (int j = 0; j < NTP; ++j) { da[j] *= SCALE_ATT; mx = fmaxf(mx, da[j]); }
        float s = 0.f;
        #pragma unroll
        for (int j = 0; j < NTP; ++j) { da[j] = __expf(da[j] - mx); s += da[j]; }
        float inv = 1.f / s;
        #pragma unroll
        for (int j = 0; j < NTP; ++j) da[j] *= inv;
    }
    {
        float mx = -1e30f;
        #pragma unroll
        for (int j = 0; j < NTP; ++j) { db[j] *= SCALE_ATT; mx = fmaxf(mx, db[j]); }
        float s = 0.f;
        #pragma unroll
        for (int j = 0; j < NTP; ++j) { db[j] = __expf(db[j] - mx); s += db[j]; }
        float inv = 1.f / s;
        #pragma unroll
        for (int j = 0; j < NTP; ++j) db[j] *= inv;
    }
    size_t o0 = (size_t)((b*TT + i0)*VV + v)*INNER + h*DH;
    size_t o1 = o0 + (size_t)VV*INNER;
    for (int dchunk = 0; dchunk < 4; ++dchunk) {
        int dbase = dchunk * 16;
        float oa[16], ob[16];
        #pragma unroll
        for (int dd = 0; dd < 16; ++dd) { oa[dd] = 0.f; ob[dd] = 0.f; }
        #pragma unroll
        for (int j = 0; j < NTP; ++j) {
            #pragma unroll
            for (int dd = 0; dd < 16; ++dd) {
                float vv = vs[j][dbase + dd];
                oa[dd] += da[j] * vv;
                ob[dd] += db[j] * vv;
            }
        }
        #pragma unroll
        for (int dd = 0; dd < 16; dd += 4) {
            *(float4*)(g_ao + o0 + dbase + dd) = *(float4*)&oa[dd];
            *(float4*)(g_ao + o1 + dbase + dd) = *(float4*)&ob[dd];
        }
    }
}

// ---------------- launch -----------------------------------------------------
extern "C" void kernel_launch(void* const* d_in, const int* in_sizes, int n_in,
                              void* d_out, int out_size) {
    (void)in_sizes; (void)n_in; (void)out_size;
    float *p_xT, *p_xn, *p_q, *p_kv, *p_ao, *p_xg, *p_wt;
    cudaGetSymbolAddress((void**)&p_xT, g_xT);
    cudaGetSymbolAddress((void**)&p_xn, g_xn);
    cudaGetSymbolAddress((void**)&p_q,  g_q);
    cudaGetSymbolAddress((void**)&p_kv, g_kv);
    cudaGetSymbolAddress((void**)&p_ao, g_ao);
    cudaGetSymbolAddress((void**)&p_xg, g_xg);
    cudaGetSymbolAddress((void**)&p_wt, g_wt);

    cudaFuncSetAttribute(k_gemm_mma<0>, cudaFuncAttributeMaxDynamicSharedMemorySize, GEMM_SMEM);
    cudaFuncSetAttribute(k_gemm_mma<2>, cudaFuncAttributeMaxDynamicSharedMemorySize, GEMM_SMEM);
    cudaFuncSetAttribute(k_gemm_mma<3>, cudaFuncAttributeMaxDynamicSharedMemorySize, GEMM_SMEM);

    const float* x      = (const float*)d_in[0];
    const float* ln1_g  = (const float*)d_in[1];
    const float* ln1_b  = (const float*)d_in[2];
    const float* la_wq  = (const float*)d_in[3];
    const float* la_wkv = (const float*)d_in[4];
    const float* la_wo  = (const float*)d_in[5];
    const float* la_bo  = (const float*)d_in[6];
    const float* ln2_g  = (const float*)d_in[7];
    const float* ln2_b  = (const float*)d_in[8];
    const float* ff1_w1 = (const float*)d_in[9];
    const float* ff1_b1 = (const float*)d_in[10];
    const float* ff1_w2 = (const float*)d_in[11];
    const float* ff1_b2 = (const float*)d_in[12];
    const float* ln3_g  = (const float*)d_in[13];
    const float* ln3_b  = (const float*)d_in[14];
    const float* ga_wq  = (const float*)d_in[15];
    const float* ga_wkv = (const float*)d_in[16];
    const float* ga_wo  = (const float*)d_in[17];
    const float* ga_bo  = (const float*)d_in[18];
    const float* ln4_g  = (const float*)d_in[19];
    const float* ln4_b  = (const float*)d_in[20];
    const float* ff2_w1 = (const float*)d_in[21];
    const float* ff2_b1 = (const float*)d_in[22];
    const float* ff2_w2 = (const float*)d_in[23];
    const float* ff2_b2 = (const float*)d_in[24];

    // pre-transpose + tf32-round all weights
    for (int l = 0; l < 2; ++l) {
        float* wb = p_wt + (size_t)l*WT_LSZ;
        #define TRN(src, off, Kd, Md) \
            k_wt<<<((Kd)*(Md) + 255)/256, 256>>>(src, wb + off, Kd, Md)
        TRN(la_wq  + (size_t)l*CC*INNER,      OFF_WQ,   CC,    INNER);
        TRN(la_wkv + (size_t)l*CC*2*INNER,    OFF_WKV,  CC,    2*INNER);
        TRN(la_wo  + (size_t)l*INNER*CC,      OFF_WO,   INNER, CC);
        TRN(ff1_w1 + (size_t)l*CC*512,        OFF_F1A,  CC,    512);
        TRN(ff1_w2 + (size_t)l*512*CC,        OFF_F1B,  512,   CC);
        TRN(ga_wq  + (size_t)l*CC*INNER,      OFF_GWQ,  CC,    INNER);
        TRN(ga_wkv + (size_t)l*CC*PP*2*INNER, OFF_GWKV, CC*PP, 2*INNER);
        TRN(ga_wo  + (size_t)l*INNER*CC,      OFF_GWO,  INNER, CC);
        TRN(ff2_w1 + (size_t)l*CC*512,        OFF_F2A,  CC,    512);
        TRN(ff2_w2 + (size_t)l*512*CC,        OFF_F2B,  512,   CC);
        #undef TRN
    }

    const int rowTiles  = (NTOK  + 127) / 128;   // 919
    const int rowTilesG = (NKTOK + 127) / 128;   // 132
    const dim3 gQ (4,  rowTiles);
    const dim3 gKV(8,  rowTiles);
    const dim3 gO (1,  rowTiles);
    const dim3 gGK(8,  rowTilesG);
    const int lnGrid = NTOK / 8;

    k_tin<<<BB*TT, 256>>>(x);
    for (int l = 0; l < 2; ++l) {
        float* wb = p_wt + (size_t)l*WT_LSZ;
        // --- local attention block ---
        k_ln<<<lnGrid, 256>>>(ln1_g + l*CC, ln1_b + l*CC);
        k_gemm_mma<0><<<gQ, 256, GEMM_SMEM>>>(p_xn, wb + OFF_WQ,  nullptr, nullptr, p_q,  NTOK, CC, INNER);
        k_gemm_mma<0><<<gKV,256, GEMM_SMEM>>>(p_xn, wb + OFF_WKV, nullptr, nullptr, p_kv, NTOK, CC, 2*INNER);
        k_lattn<<<NKTOK, 256>>>();
        k_gemm_mma<3><<<gO, 256, GEMM_SMEM>>>(p_ao, wb + OFF_WO, la_bo + l*CC, p_xT, p_xT, NTOK, INNER, CC);
        // --- ff1 ---
        k_ln<<<lnGrid, 256>>>(ln2_g + l*CC, ln2_b + l*CC);
        k_gemm_mma<2><<<gQ, 256, GEMM_SMEM>>>(p_xn, wb + OFF_F1A, ff1_b1 + l*512, nullptr, p_q, NTOK, CC, 512);
        k_gemm_mma<3><<<gO, 256, GEMM_SMEM>>>(p_q,  wb + OFF_F1B, ff1_b2 + l*CC, p_xT, p_xT, NTOK, 512, CC);
        // --- global attention block ---
        k_ln<<<lnGrid, 256>>>(ln3_g + l*CC, ln3_b + l*CC);
        k_gemm_mma<0><<<gQ, 256, GEMM_SMEM>>>(p_xn, wb + OFF_GWQ, nullptr, nullptr, p_q, NTOK, CC, INNER);
        k_gather<<<(NKTOK*896 + 255)/256, 256>>>();
        k_gemm_mma<0><<<gGK,256, GEMM_SMEM>>>(p_xg, wb + OFF_GWKV, nullptr, nullptr, p_kv, NKTOK, CC*PP, 2*INNER);
        k_gattn<<<BB*NHEAD*VV, 160>>>();
        k_gemm_mma<3><<<gO, 256, GEMM_SMEM>>>(p_ao, wb + OFF_GWO, ga_bo + l*CC, p_xT, p_xT, NTOK, INNER, CC);
        // --- ff2 ---
        k_ln<<<lnGrid, 256>>>(ln4_g + l*CC, ln4_b + l*CC);
        k_gemm_mma<2><<<gQ, 256, GEMM_SMEM>>>(p_xn, wb + OFF_F2A, ff2_b1 + l*512, nullptr, p_q, NTOK, CC, 512);
        k_gemm_mma<3><<<gO, 256, GEMM_SMEM>>>(p_q,  wb + OFF_F2B, ff2_b2 + l*CC, p_xT, p_xT, NTOK, 512, CC);
    }
    k_tout<<<BB*TT, 256>>>((float*)d_out);
}

// round 5
// speedup vs baseline: 2.3680x; 1.3287x over previous
#include <cuda_runtime.h>
#include <cuda_bf16.h>
#include <math.h>
#include <stdint.h>

// ---------------- problem constants ----------------
#define BB     16
#define CC     128
#define TT     294
#define VV     25
#define NTOK   (BB*TT*VV)        // 117600 tokens
#define INNER  512
#define NHEAD  8
#define DH     64
#define PP     7
#define NTP    42                 // T / P
#define NKTOK  (BB*NTP*VV)        // 16800 kv tokens (global)
#define SCALE_ATT 0.125f
#define LN_EPS 1e-5f

// transposed bf16 weight layout (elements, per layer)
#define OFF_LQKV  0               // [1536,128]
#define OFF_LWO   196608          // [128,512]
#define OFF_F1A   262144          // [512,128]
#define OFF_F1B   327680          // [128,512]
#define OFF_GWQ   393216          // [512,128]
#define OFF_GWKV  458752          // [1024,896] (k reordered kp*128+c)
#define OFF_GWO   1376256         // [128,512]
#define OFF_F2A   1441792         // [512,128]
#define OFF_F2B   1507328         // [128,512]
#define WT_LSZ    1572864

// ---------------- scratch (static device memory; no allocs) ----------------
__device__ __align__(16) float          g_xT[NTOK*CC];          // residual, fp32
__device__ __align__(16) __nv_bfloat16  g_xn[NTOK*CC];          // LN output
__device__ __align__(16) __nv_bfloat16  g_qkv[(size_t)NTOK*1536];
__device__ __align__(16) __nv_bfloat16  g_q [NTOK*INNER];
__device__ __align__(16) __nv_bfloat16  g_kv[NKTOK*1024];
__device__ __align__(16) __nv_bfloat16  g_ao[NTOK*INNER];       // attn out / ff hidden
__device__ __align__(16) __nv_bfloat16  g_xg[NKTOK*896];
__device__ __align__(16) __nv_bfloat16  g_wt[2*WT_LSZ];

// ---------------- helpers ----------------
__device__ __forceinline__ float2 ldbf2(const __nv_bfloat16* p) {
    return __bfloat1622float2(*reinterpret_cast<const __nv_bfloat162*>(p));
}
__device__ __forceinline__ void stbf2(__nv_bfloat16* p, float2 v) {
    *reinterpret_cast<__nv_bfloat162*>(p) = __float22bfloat162_rn(v);
}
__device__ __forceinline__ float2 u2f2(uint32_t u) {
    return __bfloat1622float2(*reinterpret_cast<const __nv_bfloat162*>(&u));
}
__device__ __forceinline__ void mma_bf16(float* d, const uint32_t* a, const uint32_t* b) {
    asm volatile(
        "mma.sync.aligned.m16n8k16.row.col.f32.bf16.bf16.f32 "
        "{%0,%1,%2,%3}, {%4,%5,%6,%7}, {%8,%9}, {%0,%1,%2,%3};"
        : "+f"(d[0]), "+f"(d[1]), "+f"(d[2]), "+f"(d[3])
        : "r"(a[0]), "r"(a[1]), "r"(a[2]), "r"(a[3]), "r"(b[0]), "r"(b[1]));
}
__device__ __forceinline__ float gelu_exact(float v) {
    return 0.5f * v * (1.0f + erff(v * 0.7071067811865475f));
}

// ---------------- transpose in: x[B,C,T,V] -> xT[(b t v), c] ----------------
__global__ void k_tin(const float* __restrict__ x) {
    int bt = blockIdx.x;
    int t = bt % TT, b = bt / TT;
    __shared__ float sm[CC*VV];
    for (int idx = threadIdx.x; idx < CC*VV; idx += blockDim.x) {
        int c = idx / VV, v = idx % VV;
        sm[idx] = x[(((size_t)b*CC + c)*TT + t)*VV + v];
    }
    __syncthreads();
    size_t base = ((size_t)(b*TT + t))*VV*CC;
    for (int idx = threadIdx.x; idx < CC*VV; idx += blockDim.x) {
        int v = idx / CC, c = idx % CC;
        g_xT[base + idx] = sm[c*VV + v];
    }
}

__global__ void k_tout(float* __restrict__ out) {
    int bt = blockIdx.x;
    int t = bt % TT, b = bt / TT;
    __shared__ float sm[CC*VV];
    size_t base = ((size_t)(b*TT + t))*VV*CC;
    for (int idx = threadIdx.x; idx < CC*VV; idx += blockDim.x)
        sm[idx] = g_xT[base + idx];
    __syncthreads();
    for (int idx = threadIdx.x; idx < CC*VV; idx += blockDim.x) {
        int c = idx / VV, v = idx % VV;
        out[(((size_t)b*CC + c)*TT + t)*VV + v] = sm[v*CC + c];
    }
}

// ---------------- weight prep: one launch per layer ------------------------
__global__ void k_wprep(const float* __restrict__ wq,  const float* __restrict__ wkv,
                        const float* __restrict__ wo,  const float* __restrict__ f1a,
                        const float* __restrict__ f1b, const float* __restrict__ gwq,
                        const float* __restrict__ gwkv,const float* __restrict__ gwo,
                        const float* __restrict__ f2a, const float* __restrict__ f2b,
                        __nv_bfloat16* __restrict__ dst)
{
    for (int idx = blockIdx.x*256 + threadIdx.x; idx < WT_LSZ; idx += gridDim.x*256) {
        float v;
        if (idx < OFF_LWO) {                      // [1536,128] <- wq[128,512]|wkv[128,1024]
            int m = idx >> 7, k = idx & 127;
            v = (m < 512) ? wq[k*512 + m] : wkv[k*1024 + (m-512)];
        } else if (idx < OFF_F1A) {               // [128,512] <- wo[512,128]
            int r = idx - OFF_LWO; int m = r >> 9, k = r & 511; v = wo[k*128 + m];
        } else if (idx < OFF_F1B) {               // [512,128] <- f1a[128,512]
            int r = idx - OFF_F1A; int m = r >> 7, k = r & 127; v = f1a[k*512 + m];
        } else if (idx < OFF_GWQ) {               // [128,512] <- f1b[512,128]
            int r = idx - OFF_F1B; int m = r >> 9, k = r & 511; v = f1b[k*128 + m];
        } else if (idx < OFF_GWKV) {              // [512,128] <- gwq[128,512]
            int r = idx - OFF_GWQ; int m = r >> 7, k = r & 127; v = gwq[k*512 + m];
        } else if (idx < OFF_GWO) {               // [1024, kp*128+c] <- gwkv[c,kp,i]
            int r = idx - OFF_GWKV; int i = r / 896; int kk = r - i*896;
            int kp = kk >> 7, c = kk & 127;
            v = gwkv[(c*PP + kp)*1024 + i];
        } else if (idx < OFF_F2A) {               // [128,512] <- gwo[512,128]
            int r = idx - OFF_GWO; int m = r >> 9, k = r & 511; v = gwo[k*128 + m];
        } else if (idx < OFF_F2B) {               // [512,128] <- f2a[128,512]
            int r = idx - OFF_F2A; int m = r >> 7, k = r & 127; v = f2a[k*512 + m];
        } else {                                  // [128,512] <- f2b[512,128]
            int r = idx - OFF_F2B; int m = r >> 9, k = r & 511; v = f2b[k*128 + m];
        }
        dst[idx] = __float2bfloat16(v);
    }
}

// ---------------- channel layernorm: fp32 in, bf16 out ----------------
__global__ void __launch_bounds__(256) k_ln(const float* __restrict__ gam,
                                            const float* __restrict__ bet) {
    int n = blockIdx.x * 8 + (threadIdx.x >> 5);
    if (n >= NTOK) return;
    int lane = threadIdx.x & 31;
    float4 a = ((const float4*)(g_xT + (size_t)n*CC))[lane];
    float s  = a.x + a.y + a.z + a.w;
    float ss = a.x*a.x + a.y*a.y + a.z*a.z + a.w*a.w;
    #pragma unroll
    for (int o = 16; o; o >>= 1) {
        s  += __shfl_xor_sync(0xffffffffu, s,  o);
        ss += __shfl_xor_sync(0xffffffffu, ss, o);
    }
    float m   = s * (1.f/128.f);
    float var = ss * (1.f/128.f) - m*m;
    float r   = rsqrtf(var + LN_EPS);
    float4 gg = ((const float4*)gam)[lane];
    float4 bb = ((const float4*)bet)[lane];
    float2 p0 = make_float2((a.x - m)*r*gg.x + bb.x, (a.y - m)*r*gg.y + bb.y);
    float2 p1 = make_float2((a.z - m)*r*gg.z + bb.z, (a.w - m)*r*gg.w + bb.w);
    uint2 st;
    __nv_bfloat162 h0 = __float22bfloat162_rn(p0);
    __nv_bfloat162 h1 = __float22bfloat162_rn(p1);
    st.x = *reinterpret_cast<uint32_t*>(&h0);
    st.y = *reinterpret_cast<uint32_t*>(&h1);
    *reinterpret_cast<uint2*>(g_xn + (size_t)n*CC + lane*4) = st;
}

// ---------------- bf16 mma GEMM: C[N,M] = A[N,K] @ Wt[M,K]^T ---------------
// 128x128 CTA tile, K-tile 32, 2-stage smem, fragment-permuted layout.
// EPI: 0 none (bf16 out), 2 bias+gelu (bf16 out), 3 bias+residual (fp32 out)
template<int EPI>
__global__ void __launch_bounds__(256) k_gemm_bf(
    const __nv_bfloat16* __restrict__ A, const __nv_bfloat16* __restrict__ Wt,
    const float* __restrict__ bias, const float* __restrict__ res,
    void* __restrict__ Cv, int Nrows, int K, int M)
{
    __shared__ uint32_t sA[2][2048];   // 8KB/stage: 8 mtiles x 2 ksteps x 32 lanes x 16B
    __shared__ uint32_t sB[2][2048];   // 8KB/stage: 16 ntiles x 2 ksteps x 32 lanes x 8B

    const int t = threadIdx.x;
    const int lane = t & 31, wid = t >> 5;
    const int wr = wid & 1, wc = wid >> 1;
    const int rowBase = blockIdx.y << 7, colBase = blockIdx.x << 7;

    const int rL = t >> 1;            // 0..127 (A row / B n-row)
    const int half = t & 1;           // kstep within k-tile
    int ga = rowBase + rL; if (ga >= Nrows) ga = Nrows - 1;
    const __nv_bfloat16* aP = A  + (size_t)ga * K + (half << 4);
    const __nv_bfloat16* bP = Wt + (size_t)(colBase + rL) * K + (half << 4);

    // permuted-store base indices (uint32 units)
    const int aBase = (((rL >> 4)*2 + half)*32 + (rL & 7)*4)*4 + ((rL >> 3) & 1);
    const int bBase = (((rL >> 3)*2 + half)*32 + (rL & 7)*4)*2;

    float acc[4][4][4];
    #pragma unroll
    for (int mt = 0; mt < 4; ++mt)
        #pragma unroll
        for (int nt = 0; nt < 4; ++nt)
            #pragma unroll
            for (int e = 0; e < 4; ++e) acc[mt][nt][e] = 0.f;

    const int nk = K >> 5;

    uint4 ua, ua2, ub, ub2;
    ua  = *(const uint4*)(aP);      ua2 = *(const uint4*)(aP + 8);
    ub  = *(const uint4*)(bP);      ub2 = *(const uint4*)(bP + 8);
    {   // stage 0
        uint32_t* As = sA[0]; uint32_t* Bs = sB[0];
        As[aBase+0]=ua.x;  As[aBase+4]=ua.y;  As[aBase+8]=ua.z;   As[aBase+12]=ua.w;
        As[aBase+2]=ua2.x; As[aBase+6]=ua2.y; As[aBase+10]=ua2.z; As[aBase+14]=ua2.w;
        Bs[bBase+0]=ub.x;  Bs[bBase+2]=ub.y;  Bs[bBase+4]=ub.z;   Bs[bBase+6]=ub.w;
        Bs[bBase+1]=ub2.x; Bs[bBase+3]=ub2.y; Bs[bBase+5]=ub2.z;  Bs[bBase+7]=ub2.w;
    }
    __syncthreads();

    for (int kt = 0; kt < nk; ++kt) {
        const int s = kt & 1;
        const bool more = (kt + 1 < nk);
        if (more) {
            const int ko = (kt + 1) << 5;
            ua  = *(const uint4*)(aP + ko);      ua2 = *(const uint4*)(aP + ko + 8);
            ub  = *(const uint4*)(bP + ko);      ub2 = *(const uint4*)(bP + ko + 8);
        }
        // compute stage s
        #pragma unroll
        for (int ks = 0; ks < 2; ++ks) {
            uint32_t afr[4][4];
            uint32_t bfr[4][2];
            #pragma unroll
            for (int mt = 0; mt < 4; ++mt)
                *(uint4*)afr[mt] = *(const uint4*)&sA[s][(((wr*4+mt)*2 + ks)*32 + lane)*4];
            #pragma unroll
            for (int nt = 0; nt < 4; ++nt)
                *(uint2*)bfr[nt] = *(const uint2*)&sB[s][(((wc*4+nt)*2 + ks)*32 + lane)*2];
            #pragma unroll
            for (int mt = 0; mt < 4; ++mt)
                #pragma unroll
                for (int nt = 0; nt < 4; ++nt)
                    mma_bf16(acc[mt][nt], afr[mt], bfr[nt]);
        }
        if (more) {
            uint32_t* As = sA[s^1]; uint32_t* Bs = sB[s^1];
            As[aBase+0]=ua.x;  As[aBase+4]=ua.y;  As[aBase+8]=ua.z;   As[aBase+12]=ua.w;
            As[aBase+2]=ua2.x; As[aBase+6]=ua2.y; As[aBase+10]=ua2.z; As[aBase+14]=ua2.w;
            Bs[bBase+0]=ub.x;  Bs[bBase+2]=ub.y;  Bs[bBase+4]=ub.z;   Bs[bBase+6]=ub.w;
            Bs[bBase+1]=ub2.x; Bs[bBase+3]=ub2.y; Bs[bBase+5]=ub2.z;  Bs[bBase+7]=ub2.w;
        }
        __syncthreads();
    }

    // ---------------- epilogue ----------------
    #pragma unroll
    for (int nt = 0; nt < 4; ++nt) {
        const int col = colBase + wc*32 + nt*8 + (lane & 3)*2;
        float2 bb = make_float2(0.f, 0.f);
        if (EPI >= 1) bb = *(const float2*)(bias + col);
        #pragma unroll
        for (int mt = 0; mt < 4; ++mt) {
            const int row0 = rowBase + wr*64 + mt*16 + (lane >> 2);
            #pragma unroll
            for (int hf = 0; hf < 2; ++hf) {
                const int r = row0 + hf*8;
                if (r >= Nrows) continue;
                float2 o = make_float2(acc[mt][nt][hf*2+0] + bb.x,
                                       acc[mt][nt][hf*2+1] + bb.y);
                if (EPI == 2) { o.x = gelu_exact(o.x); o.y = gelu_exact(o.y); }
                if (EPI == 3) {
                    float2 rv = *(const float2*)(res + (size_t)r*M + col);
                    o.x += rv.x; o.y += rv.y;
                    *(float2*)((float*)Cv + (size_t)r*M + col) = o;
                } else {
                    stbf2((__nv_bfloat16*)Cv + (size_t)r*M + col, o);
                }
            }
        }
    }
}

// ---------------- local attention: one warp per (b, patch, v, head) --------
__global__ void __launch_bounds__(256) k_lattn() {
    int w = blockIdx.x * 8 + (threadIdx.x >> 5);
    int lane = threadIdx.x & 31;
    int h = w & 7;
    int g = w >> 3;
    int v = g % VV;
    int r = g / VV;
    int tt = r % NTP;
    int b = r / NTP;
    int d0 = lane * 2;

    float2 q[PP], kk[PP], vv[PP];
    #pragma unroll
    for (int p = 0; p < PP; ++p) {
        int n = (b*TT + tt*PP + p)*VV + v;
        const __nv_bfloat16* rowp = g_qkv + (size_t)n*1536 + h*DH + d0;
        q[p]  = ldbf2(rowp);
        kk[p] = ldbf2(rowp + 512);
        vv[p] = ldbf2(rowp + 1024);
    }
    float dots[PP][PP];
    #pragma unroll
    for (int i = 0; i < PP; ++i)
        #pragma unroll
        for (int j = 0; j < PP; ++j)
            dots[i][j] = q[i].x*kk[j].x + q[i].y*kk[j].y;
    #pragma unroll
    for (int o = 16; o; o >>= 1)
        #pragma unroll
        for (int i = 0; i < PP; ++i)
            #pragma unroll
            for (int j = 0; j < PP; ++j)
                dots[i][j] += __shfl_xor_sync(0xffffffffu, dots[i][j], o);
    #pragma unroll
    for (int i = 0; i < PP; ++i) {
        float mx = -1e30f;
        #pragma unroll
        for (int j = 0; j < PP; ++j) {
            dots[i][j] *= SCALE_ATT;
            mx = fmaxf(mx, dots[i][j]);
        }
        float s = 0.f;
        #pragma unroll
        for (int j = 0; j < PP; ++j) { dots[i][j] = __expf(dots[i][j] - mx); s += dots[i][j]; }
        float inv = 1.f / s;
        #pragma unroll
        for (int j = 0; j < PP; ++j) dots[i][j] *= inv;
    }
    #pragma unroll
    for (int i = 0; i < PP; ++i) {
        float2 o = make_float2(0.f, 0.f);
        #pragma unroll
        for (int j = 0; j < PP; ++j) {
            o.x += dots[i][j] * vv[j].x;
            o.y += dots[i][j] * vv[j].y;
        }
        int n = (b*TT + tt*PP + i)*VV + v;
        stbf2(g_ao + (size_t)n*INNER + h*DH + d0, o);
    }
}

// ---------------- gather (coalesced row copies) -----------------------------
__global__ void k_gather() {
    int idx = blockIdx.x * 256 + threadIdx.x;     // over NKTOK * 7 * 16 (uint4 of 8 bf16)
    if (idx >= NKTOK*112) return;
    int nk = idx / 112;
    int rem = idx - nk*112;
    int kp = rem >> 4, u = rem & 15;
    int v  = nk % VV;
    int rr = nk / VV;
    int tt = rr % NTP;
    int b  = rr / NTP;
    int src = ((b*TT + tt*PP + kp)*VV + v)*CC + u*8;
    *reinterpret_cast<uint4*>(g_xg + (size_t)nk*896 + kp*128 + u*8) =
        *reinterpret_cast<const uint4*>(g_xn + src);
}

// ---------------- global attention: one block per (b, h, v) ----------------
__global__ void __launch_bounds__(160) k_gattn() {
    int bid = blockIdx.x;
    int v = bid % VV;
    int rr = bid / VV;
    int h = rr & 7;
    int b = rr >> 3;
    __shared__ float ks[NTP][DH];
    __shared__ float vs[NTP][DH];
    for (int idx = threadIdx.x; idx < NTP*DH/2; idx += 160) {
        int j = idx >> 5, d2 = idx & 31;
        int nk = (b*NTP + j)*VV + v;
        size_t o = (size_t)nk*1024 + h*DH + d2*2;
        float2 kf = ldbf2(g_kv + o);
        float2 vf = ldbf2(g_kv + o + 512);
        ks[j][d2*2] = kf.x; ks[j][d2*2+1] = kf.y;
        vs[j][d2*2] = vf.x; vs[j][d2*2+1] = vf.y;
    }
    __syncthreads();
    int tid = threadIdx.x;
    if (tid >= 147) return;
    int i0 = 2*tid;
    size_t q0 = (size_t)((b*TT + i0)*VV + v)*INNER + h*DH;
    size_t q1 = q0 + (size_t)VV*INNER;

    float da[NTP], db[NTP];
    #pragma unroll
    for (int j = 0; j < NTP; ++j) { da[j] = 0.f; db[j] = 0.f; }

    for (int dchunk = 0; dchunk < 4; ++dchunk) {
        int dbase = dchunk * 16;
        float qa[16], qb[16];
        {
            uint4 u0 = *(const uint4*)(g_q + q0 + dbase);
            uint4 u1 = *(const uint4*)(g_q + q0 + dbase + 8);
            uint4 w0 = *(const uint4*)(g_q + q1 + dbase);
            uint4 w1 = *(const uint4*)(g_q + q1 + dbase + 8);
            float2 f;
            f=u2f2(u0.x); qa[0]=f.x; qa[1]=f.y;  f=u2f2(u0.y); qa[2]=f.x; qa[3]=f.y;
            f=u2f2(u0.z); qa[4]=f.x; qa[5]=f.y;  f=u2f2(u0.w); qa[6]=f.x; qa[7]=f.y;
            f=u2f2(u1.x); qa[8]=f.x; qa[9]=f.y;  f=u2f2(u1.y); qa[10]=f.x; qa[11]=f.y;
            f=u2f2(u1.z); qa[12]=f.x; qa[13]=f.y; f=u2f2(u1.w); qa[14]=f.x; qa[15]=f.y;
            f=u2f2(w0.x); qb[0]=f.x; qb[1]=f.y;  f=u2f2(w0.y); qb[2]=f.x; qb[3]=f.y;
            f=u2f2(w0.z); qb[4]=f.x; qb[5]=f.y;  f=u2f2(w0.w); qb[6]=f.x; qb[7]=f.y;
            f=u2f2(w1.x); qb[8]=f.x; qb[9]=f.y;  f=u2f2(w1.y); qb[10]=f.x; qb[11]=f.y;
            f=u2f2(w1.z); qb[12]=f.x; qb[13]=f.y; f=u2f2(w1.w); qb[14]=f.x; qb[15]=f.y;
        }
        #pragma unroll
        for (int j = 0; j < NTP; ++j) {
            #pragma unroll
            for (int dd = 0; dd < 16; ++dd) {
                float kv = ks[j][dbase + dd];
                da[j] += qa[dd] * kv;
                db[j] += qb[dd] * kv;
            }
        }
    }
    {
        float mx = -1e30f;
        #pragma unroll
        for (int j = 0; j < NTP; ++j) { da[j] *= SCALE_ATT; mx = fmaxf(mx, da[j]); }
        float s = 0.f;
        #pragma unroll
        for (int j = 0; j < NTP; ++j) { da[j] = __expf(da[j] - mx); s += da[j]; }
        float inv = 1.f / s;
        #pragma unroll
        for (int j = 0; j < NTP; ++j) da[j] *= inv;
    }
    {
        float mx = -1e30f;
        #pragma unroll
        for (int j = 0; j < NTP; ++j) { db[j] *= SCALE_ATT; mx = fmaxf(mx, db[j]); }
        float s = 0.f;
        #pragma unroll
        for (int j = 0; j < NTP; ++j) { db[j] = __expf(db[j] - mx); s += db[j]; }
        float inv = 1.f / s;
        #pragma unroll
        for (int j = 0; j < NTP; ++j) db[j] *= inv;
    }
    size_t o0 = q0, o1 = q1;   // ao has same [N,512] layout
    for (int dchunk = 0; dchunk < 4; ++dchunk) {
        int dbase = dchunk * 16;
        float oa[16], ob[16];
        #pragma unroll
        for (int dd = 0; dd < 16; ++dd) { oa[dd] = 0.f; ob[dd] = 0.f; }
        #pragma unroll
        for (int j = 0; j < NTP; ++j) {
            #pragma unroll
            for (int dd = 0; dd < 16; ++dd) {
                float vv = vs[j][dbase + dd];
                oa[dd] += da[j] * vv;
                ob[dd] += db[j] * vv;
            }
        }
        #pragma unroll
        for (int dd = 0; dd < 16; dd += 2) {
            stbf2(g_ao + o0 + dbase + dd, make_float2(oa[dd], oa[dd+1]));
            stbf2(g_ao + o1 + dbase + dd, make_float2(ob[dd], ob[dd+1]));
        }
    }
}

// ---------------- launch -----------------------------------------------------
extern "C" void kernel_launch(void* const* d_in, const int* in_sizes, int n_in,
                              void* d_out, int out_size) {
    (void)in_sizes; (void)n_in; (void)out_size;
    float* p_xT;
    __nv_bfloat16 *p_xn, *p_qkv, *p_q, *p_kv, *p_ao, *p_xg, *p_wt;
    cudaGetSymbolAddress((void**)&p_xT,  g_xT);
    cudaGetSymbolAddress((void**)&p_xn,  g_xn);
    cudaGetSymbolAddress((void**)&p_qkv, g_qkv);
    cudaGetSymbolAddress((void**)&p_q,   g_q);
    cudaGetSymbolAddress((void**)&p_kv,  g_kv);
    cudaGetSymbolAddress((void**)&p_ao,  g_ao);
    cudaGetSymbolAddress((void**)&p_xg,  g_xg);
    cudaGetSymbolAddress((void**)&p_wt,  g_wt);

    const float* x      = (const float*)d_in[0];
    const float* ln1_g  = (const float*)d_in[1];
    const float* ln1_b  = (const float*)d_in[2];
    const float* la_wq  = (const float*)d_in[3];
    const float* la_wkv = (const float*)d_in[4];
    const float* la_wo  = (const float*)d_in[5];
    const float* la_bo  = (const float*)d_in[6];
    const float* ln2_g  = (const float*)d_in[7];
    const float* ln2_b  = (const float*)d_in[8];
    const float* ff1_w1 = (const float*)d_in[9];
    const float* ff1_b1 = (const float*)d_in[10];
    const float* ff1_w2 = (const float*)d_in[11];
    const float* ff1_b2 = (const float*)d_in[12];
    const float* ln3_g  = (const float*)d_in[13];
    const float* ln3_b  = (const float*)d_in[14];
    const float* ga_wq  = (const float*)d_in[15];
    const float* ga_wkv = (const float*)d_in[16];
    const float* ga_wo  = (const float*)d_in[17];
    const float* ga_bo  = (const float*)d_in[18];
    const float* ln4_g  = (const float*)d_in[19];
    const float* ln4_b  = (const float*)d_in[20];
    const float* ff2_w1 = (const float*)d_in[21];
    const float* ff2_b1 = (const float*)d_in[22];
    const float* ff2_w2 = (const float*)d_in[23];
    const float* ff2_b2 = (const float*)d_in[24];

    // weight prep: 2 launches
    for (int l = 0; l < 2; ++l) {
        k_wprep<<<4096, 256>>>(
            la_wq  + (size_t)l*CC*INNER,      la_wkv + (size_t)l*CC*2*INNER,
            la_wo  + (size_t)l*INNER*CC,      ff1_w1 + (size_t)l*CC*512,
            ff1_w2 + (size_t)l*512*CC,        ga_wq  + (size_t)l*CC*INNER,
            ga_wkv + (size_t)l*CC*PP*2*INNER, ga_wo  + (size_t)l*INNER*CC,
            ff2_w1 + (size_t)l*CC*512,        ff2_w2 + (size_t)l*512*CC,
            p_wt + (size_t)l*WT_LSZ);
    }

    const int rowTiles  = (NTOK  + 127) / 128;   // 919
    const int rowTilesG = (NKTOK + 127) / 128;   // 132
    const int lnGrid = NTOK / 8;                 // 14700

    k_tin<<<BB*TT, 256>>>(x);
    for (int l = 0; l < 2; ++l) {
        __nv_bfloat16* wb = p_wt + (size_t)l*WT_LSZ;
        // --- local attention block ---
        k_ln<<<lnGrid, 256>>>(ln1_g + l*CC, ln1_b + l*CC);
        k_gemm_bf<0><<<dim3(12, rowTiles), 256>>>(p_xn, wb + OFF_LQKV, nullptr, nullptr, p_qkv, NTOK, 128, 1536);
        k_lattn<<<NKTOK, 256>>>();
        k_gemm_bf<3><<<dim3(1, rowTiles), 256>>>(p_ao, wb + OFF_LWO, la_bo + l*CC, p_xT, p_xT, NTOK, 512, 128);
        // --- ff1 ---
        k_ln<<<lnGrid, 256>>>(ln2_g + l*CC, ln2_b + l*CC);
        k_gemm_bf<2><<<dim3(4, rowTiles), 256>>>(p_xn, wb + OFF_F1A, ff1_b1 + l*512, nullptr, p_ao, NTOK, 128, 512);
        k_gemm_bf<3><<<dim3(1, rowTiles), 256>>>(p_ao, wb + OFF_F1B, ff1_b2 + l*CC, p_xT, p_xT, NTOK, 512, 128);
        // --- global attention block ---
        k_ln<<<lnGrid, 256>>>(ln3_g + l*CC, ln3_b + l*CC);
        k_gemm_bf<0><<<dim3(4, rowTiles), 256>>>(p_xn, wb + OFF_GWQ, nullptr, nullptr, p_q, NTOK, 128, 512);
        k_gather<<<(NKTOK*112 + 255)/256, 256>>>();
        k_gemm_bf<0><<<dim3(8, rowTilesG), 256>>>(p_xg, wb + OFF_GWKV, nullptr, nullptr, p_kv, NKTOK, 896, 1024);
        k_gattn<<<BB*NHEAD*VV, 160>>>();
        k_gemm_bf<3><<<dim3(1, rowTiles), 256>>>(p_ao, wb + OFF_GWO, ga_bo + l*CC, p_xT, p_xT, NTOK, 512, 128);
        // --- ff2 ---
        k_ln<<<lnGrid, 256>>>(ln4_g + l*CC, ln4_b + l*CC);
        k_gemm_bf<2><<<dim3(4, rowTiles), 256>>>(p_xn, wb + OFF_F2A, ff2_b1 + l*512, nullptr, p_ao, NTOK, 128, 512);
        k_gemm_bf<3><<<dim3(1, rowTiles), 256>>>(p_ao, wb + OFF_F2B, ff2_b2 + l*CC, p_xT, p_xT, NTOK, 512, 128);
    }
    k_tout<<<BB*TT, 256>>>((float*)d_out);
}

// round 6
// speedup vs baseline: 3.5830x; 1.5131x over previous
#include <cuda_runtime.h>
#include <cuda_bf16.h>
#include <math.h>
#include <stdint.h>

// ---------------- problem constants ----------------
#define BB     16
#define CC     128
#define TT     294
#define VV     25
#define NTOK   (BB*TT*VV)        // 117600 tokens
#define INNER  512
#define NHEAD  8
#define DH     64
#define PP     7
#define NTP    42                 // T / P
#define NKTOK  (BB*NTP*VV)        // 16800 kv tokens (global)
#define SCALE_ATT 0.125f
#define LN_EPS 1e-5f

// transposed bf16 weight layout (elements, per layer)
#define OFF_LQKV  0               // [1536,128]
#define OFF_LWO   196608          // [128,512]
#define OFF_F1A   262144          // [512,128]
#define OFF_F1B   327680          // [128,512]
#define OFF_GWQ   393216          // [512,128]
#define OFF_GWKV  458752          // [1024,896] (k reordered kp*128+c)
#define OFF_GWO   1376256         // [128,512]
#define OFF_F2A   1441792         // [512,128]
#define OFF_F2B   1507328         // [128,512]
#define WT_LSZ    1572864

// ---------------- scratch (static device memory; no allocs) ----------------
__device__ __align__(16) float          g_xT[NTOK*CC];          // residual, fp32
__device__ __align__(16) __nv_bfloat16  g_xn[NTOK*CC];          // LN output
__device__ __align__(16) __nv_bfloat16  g_qkv[(size_t)NTOK*1536];
__device__ __align__(16) __nv_bfloat16  g_q [NTOK*INNER];
__device__ __align__(16) __nv_bfloat16  g_kv[NKTOK*1024];
__device__ __align__(16) __nv_bfloat16  g_ao[NTOK*INNER];       // attn out / ff hidden
__device__ __align__(16) __nv_bfloat16  g_xg[NKTOK*896];
__device__ __align__(16) __nv_bfloat16  g_wt[2*WT_LSZ];

// ---------------- helpers ----------------
__device__ __forceinline__ uint32_t smem_u32(const void* p) {
    uint32_t a;
    asm("{ .reg .u64 t; cvta.to.shared.u64 t, %1; cvt.u32.u64 %0, t; }" : "=r"(a) : "l"(p));
    return a;
}
__device__ __forceinline__ float2 ldbf2(const __nv_bfloat16* p) {
    return __bfloat1622float2(*reinterpret_cast<const __nv_bfloat162*>(p));
}
__device__ __forceinline__ void stbf2(__nv_bfloat16* p, float2 v) {
    *reinterpret_cast<__nv_bfloat162*>(p) = __float22bfloat162_rn(v);
}
__device__ __forceinline__ float2 u2f2(uint32_t u) {
    return __bfloat1622float2(*reinterpret_cast<const __nv_bfloat162*>(&u));
}
__device__ __forceinline__ void mma_bf16(float* d, const uint32_t* a, const uint32_t* b) {
    asm volatile(
        "mma.sync.aligned.m16n8k16.row.col.f32.bf16.bf16.f32 "
        "{%0,%1,%2,%3}, {%4,%5,%6,%7}, {%8,%9}, {%0,%1,%2,%3};"
        : "+f"(d[0]), "+f"(d[1]), "+f"(d[2]), "+f"(d[3])
        : "r"(a[0]), "r"(a[1]), "r"(a[2]), "r"(a[3]), "r"(b[0]), "r"(b[1]));
}
__device__ __forceinline__ float gelu_exact(float v) {
    return 0.5f * v * (1.0f + erff(v * 0.7071067811865475f));
}

// ---------------- transpose in: x[B,C,T,V] -> xT[(b t v), c] ----------------
__global__ void k_tin(const float* __restrict__ x) {
    int bt = blockIdx.x;
    int t = bt % TT, b = bt / TT;
    __shared__ float sm[CC*VV];
    for (int idx = threadIdx.x; idx < CC*VV; idx += blockDim.x) {
        int c = idx / VV, v = idx % VV;
        sm[idx] = x[(((size_t)b*CC + c)*TT + t)*VV + v];
    }
    __syncthreads();
    size_t base = ((size_t)(b*TT + t))*VV*CC;
    for (int idx = threadIdx.x; idx < CC*VV; idx += blockDim.x) {
        int v = idx / CC, c = idx % CC;
        g_xT[base + idx] = sm[c*VV + v];
    }
}

__global__ void k_tout(float* __restrict__ out) {
    int bt = blockIdx.x;
    int t = bt % TT, b = bt / TT;
    __shared__ float sm[CC*VV];
    size_t base = ((size_t)(b*TT + t))*VV*CC;
    for (int idx = threadIdx.x; idx < CC*VV; idx += blockDim.x)
        sm[idx] = g_xT[base + idx];
    __syncthreads();
    for (int idx = threadIdx.x; idx < CC*VV; idx += blockDim.x) {
        int c = idx / VV, v = idx % VV;
        out[(((size_t)b*CC + c)*TT + t)*VV + v] = sm[v*CC + c];
    }
}

// ---------------- weight prep: one launch per layer ------------------------
__global__ void k_wprep(const float* __restrict__ wq,  const float* __restrict__ wkv,
                        const float* __restrict__ wo,  const float* __restrict__ f1a,
                        const float* __restrict__ f1b, const float* __restrict__ gwq,
                        const float* __restrict__ gwkv,const float* __restrict__ gwo,
                        const float* __restrict__ f2a, const float* __restrict__ f2b,
                        __nv_bfloat16* __restrict__ dst)
{
    for (int idx = blockIdx.x*256 + threadIdx.x; idx < WT_LSZ; idx += gridDim.x*256) {
        float v;
        if (idx < OFF_LWO) {                      // [1536,128] <- wq[128,512]|wkv[128,1024]
            int m = idx >> 7, k = idx & 127;
            v = (m < 512) ? wq[k*512 + m] : wkv[k*1024 + (m-512)];
        } else if (idx < OFF_F1A) {               // [128,512] <- wo[512,128]
            int r = idx - OFF_LWO; int m = r >> 9, k = r & 511; v = wo[k*128 + m];
        } else if (idx < OFF_F1B) {               // [512,128] <- f1a[128,512]
            int r = idx - OFF_F1A; int m = r >> 7, k = r & 127; v = f1a[k*512 + m];
        } else if (idx < OFF_GWQ) {               // [128,512] <- f1b[512,128]
            int r = idx - OFF_F1B; int m = r >> 9, k = r & 511; v = f1b[k*128 + m];
        } else if (idx < OFF_GWKV) {              // [512,128] <- gwq[128,512]
            int r = idx - OFF_GWQ; int m = r >> 7, k = r & 127; v = gwq[k*512 + m];
        } else if (idx < OFF_GWO) {               // [1024, kp*128+c] <- gwkv[c,kp,i]
            int r = idx - OFF_GWKV; int i = r / 896; int kk = r - i*896;
            int kp = kk >> 7, c = kk & 127;
            v = gwkv[(c*PP + kp)*1024 + i];
        } else if (idx < OFF_F2A) {               // [128,512] <- gwo[512,128]
            int r = idx - OFF_GWO; int m = r >> 9, k = r & 511; v = gwo[k*128 + m];
        } else if (idx < OFF_F2B) {               // [512,128] <- f2a[128,512]
            int r = idx - OFF_F2A; int m = r >> 7, k = r & 127; v = f2a[k*512 + m];
        } else {                                  // [128,512] <- f2b[512,128]
            int r = idx - OFF_F2B; int m = r >> 9, k = r & 511; v = f2b[k*128 + m];
        }
        dst[idx] = __float2bfloat16(v);
    }
}

// ---------------- channel layernorm: fp32 in, bf16 out ----------------
__global__ void __launch_bounds__(256) k_ln(const float* __restrict__ gam,
                                            const float* __restrict__ bet) {
    int n = blockIdx.x * 8 + (threadIdx.x >> 5);
    if (n >= NTOK) return;
    int lane = threadIdx.x & 31;
    float4 a = ((const float4*)(g_xT + (size_t)n*CC))[lane];
    float s  = a.x + a.y + a.z + a.w;
    float ss = a.x*a.x + a.y*a.y + a.z*a.z + a.w*a.w;
    #pragma unroll
    for (int o = 16; o; o >>= 1) {
        s  += __shfl_xor_sync(0xffffffffu, s,  o);
        ss += __shfl_xor_sync(0xffffffffu, ss, o);
    }
    float m   = s * (1.f/128.f);
    float var = ss * (1.f/128.f) - m*m;
    float r   = rsqrtf(var + LN_EPS);
    float4 gg = ((const float4*)gam)[lane];
    float4 bb = ((const float4*)bet)[lane];
    float2 p0 = make_float2((a.x - m)*r*gg.x + bb.x, (a.y - m)*r*gg.y + bb.y);
    float2 p1 = make_float2((a.z - m)*r*gg.z + bb.z, (a.w - m)*r*gg.w + bb.w);
    uint2 st;
    __nv_bfloat162 h0 = __float22bfloat162_rn(p0);
    __nv_bfloat162 h1 = __float22bfloat162_rn(p1);
    st.x = *reinterpret_cast<uint32_t*>(&h0);
    st.y = *reinterpret_cast<uint32_t*>(&h1);
    *reinterpret_cast<uint2*>(g_xn + (size_t)n*CC + lane*4) = st;
}

// ---------------- bf16 mma GEMM: C[N,M] = A[N,K] @ Wt[M,K]^T ---------------
// 128x128 CTA tile, K-tile 32, 4-stage cp.async ring, ldmatrix fragments,
// swizzled row-major smem (chunk ^= (row>>1)&3). 2 CTAs/SM.
// EPI: 0 none (bf16 out), 2 bias+gelu (bf16 out), 3 bias+residual (fp32 out)
#define GSTAGE_BYTES 16384
#define GEMM_SMEM   (4*GSTAGE_BYTES)

template<int EPI>
__global__ void __launch_bounds__(256, 2) k_gemm_bf(
    const __nv_bfloat16* __restrict__ A, const __nv_bfloat16* __restrict__ Wt,
    const float* __restrict__ bias, const float* __restrict__ res,
    void* __restrict__ Cv, int Nrows, int K, int M)
{
    extern __shared__ char smraw[];
    const uint32_t smb = smem_u32(smraw);

    const int t = threadIdx.x;
    const int lane = t & 31, wid = t >> 5;
    const int wr = wid & 1, wc = wid >> 1;
    const int rowBase = blockIdx.y << 7, colBase = blockIdx.x << 7;

    // ---- staging (cp.async): thread owns row rL, k-half `half` of each tile
    const int rL = t >> 1, half = t & 1;
    int ga = rowBase + rL; if (ga >= Nrows) ga = Nrows - 1;
    const __nv_bfloat16* aP = A  + (size_t)ga * K + (half << 4);
    const __nv_bfloat16* bP = Wt + (size_t)(colBase + rL) * K + (half << 4);
    const int fL = (rL >> 1) & 3;
    const uint32_t dA = rL*64 + 16*((2*half) ^ fL);
    const uint32_t dB = 8192 + dA;

    // ---- ldmatrix lane addressing
    const int rA  = (lane & 7) + ((lane >> 3) & 1) * 8;  // A row within 16
    const int ca  = lane >> 4;                            // A chunk offset
    const int fra = (rA >> 1) & 3;
    const int g   = lane >> 3;
    const int nB  = ((g >> 1) & 1) * 8 + (lane & 7);     // B n-row within 16
    const int cb  = g & 1;                                // B chunk offset
    const int fnb = (nB >> 1) & 3;

    float acc[4][4][4];
    #pragma unroll
    for (int mt = 0; mt < 4; ++mt)
        #pragma unroll
        for (int nt = 0; nt < 4; ++nt)
            #pragma unroll
            for (int e = 0; e < 4; ++e) acc[mt][nt][e] = 0.f;

    const int nk = K >> 5;   // always >= 4 here

    #define G_ISSUE(kt_) do {                                                   \
        const uint32_t st_ = smb + ((kt_) & 3) * GSTAGE_BYTES;                   \
        size_t sa_ = __cvta_generic_to_global(aP + ((kt_) << 5));                \
        size_t sb_ = __cvta_generic_to_global(bP + ((kt_) << 5));                \
        uint32_t a1_ = st_ + dA, b1_ = st_ + dB;                                 \
        asm volatile("cp.async.cg.shared.global [%0], [%1], 16;" :: "r"(a1_), "l"(sa_)); \
        asm volatile("cp.async.cg.shared.global [%0], [%1], 16;" :: "r"(a1_ ^ 16u), "l"(sa_ + 16)); \
        asm volatile("cp.async.cg.shared.global [%0], [%1], 16;" :: "r"(b1_), "l"(sb_)); \
        asm volatile("cp.async.cg.shared.global [%0], [%1], 16;" :: "r"(b1_ ^ 16u), "l"(sb_ + 16)); \
    } while (0)

    G_ISSUE(0); asm volatile("cp.async.commit_group;");
    G_ISSUE(1); asm volatile("cp.async.commit_group;");
    G_ISSUE(2); asm volatile("cp.async.commit_group;");

    for (int kt = 0; kt < nk; ++kt) {
        asm volatile("cp.async.wait_group 2;");
        __syncthreads();
        if (kt + 3 < nk) G_ISSUE(kt + 3);
        asm volatile("cp.async.commit_group;");

        const uint32_t stA = smb + (kt & 3) * GSTAGE_BYTES;
        const uint32_t stB = stA + 8192;
        #pragma unroll
        for (int ks = 0; ks < 2; ++ks) {
            uint32_t af[4][4], bf[4][2];
            #pragma unroll
            for (int mt = 0; mt < 4; ++mt) {
                uint32_t addr = stA + (uint32_t)((wr*64 + mt*16 + rA)*64)
                              + 16u*(uint32_t)(((ks<<1) + ca) ^ fra);
                asm volatile("ldmatrix.sync.aligned.m8n8.x4.shared.b16 {%0,%1,%2,%3}, [%4];"
                    : "=r"(af[mt][0]), "=r"(af[mt][1]), "=r"(af[mt][2]), "=r"(af[mt][3])
                    : "r"(addr));
            }
            #pragma unroll
            for (int j = 0; j < 2; ++j) {
                int n = wc*32 + j*16 + nB;
                uint32_t addr = stB + (uint32_t)(n*64)
                              + 16u*(uint32_t)(((ks<<1) + cb) ^ fnb);
                asm volatile("ldmatrix.sync.aligned.m8n8.x4.shared.b16 {%0,%1,%2,%3}, [%4];"
                    : "=r"(bf[2*j][0]), "=r"(bf[2*j][1]), "=r"(bf[2*j+1][0]), "=r"(bf[2*j+1][1])
                    : "r"(addr));
            }
            #pragma unroll
            for (int mt = 0; mt < 4; ++mt)
                #pragma unroll
                for (int nt = 0; nt < 4; ++nt)
                    mma_bf16(acc[mt][nt], af[mt], bf[nt]);
        }
    }
    #undef G_ISSUE

    // ---------------- epilogue ----------------
    #pragma unroll
    for (int nt = 0; nt < 4; ++nt) {
        const int col = colBase + wc*32 + nt*8 + (lane & 3)*2;
        float2 bb = make_float2(0.f, 0.f);
        if (EPI >= 1) bb = *(const float2*)(bias + col);
        #pragma unroll
        for (int mt = 0; mt < 4; ++mt) {
            const int row0 = rowBase + wr*64 + mt*16 + (lane >> 2);
            #pragma unroll
            for (int hf = 0; hf < 2; ++hf) {
                const int r = row0 + hf*8;
                if (r >= Nrows) continue;
                float2 o = make_float2(acc[mt][nt][hf*2+0] + bb.x,
                                       acc[mt][nt][hf*2+1] + bb.y);
                if (EPI == 2) { o.x = gelu_exact(o.x); o.y = gelu_exact(o.y); }
                if (EPI == 3) {
                    float2 rv = *(const float2*)(res + (size_t)r*M + col);
                    o.x += rv.x; o.y += rv.y;
                    *(float2*)((float*)Cv + (size_t)r*M + col) = o;
                } else {
                    stbf2((__nv_bfloat16*)Cv + (size_t)r*M + col, o);
                }
            }
        }
    }
}

// ---------------- local attention: one warp per (b, patch, v, head) --------
__global__ void __launch_bounds__(256) k_lattn() {
    int w = blockIdx.x * 8 + (threadIdx.x >> 5);
    int lane = threadIdx.x & 31;
    int h = w & 7;
    int g = w >> 3;
    int v = g % VV;
    int r = g / VV;
    int tt = r % NTP;
    int b = r / NTP;
    int d0 = lane * 2;

    float2 q[PP], kk[PP], vv[PP];
    #pragma unroll
    for (int p = 0; p < PP; ++p) {
        int n = (b*TT + tt*PP + p)*VV + v;
        const __nv_bfloat16* rowp = g_qkv + (size_t)n*1536 + h*DH + d0;
        q[p]  = ldbf2(rowp);
        kk[p] = ldbf2(rowp + 512);
        vv[p] = ldbf2(rowp + 1024);
    }
    float dots[PP][PP];
    #pragma unroll
    for (int i = 0; i < PP; ++i)
        #pragma unroll
        for (int j = 0; j < PP; ++j)
            dots[i][j] = q[i].x*kk[j].x + q[i].y*kk[j].y;
    #pragma unroll
    for (int o = 16; o; o >>= 1)
        #pragma unroll
        for (int i = 0; i < PP; ++i)
            #pragma unroll
            for (int j = 0; j < PP; ++j)
                dots[i][j] += __shfl_xor_sync(0xffffffffu, dots[i][j], o);
    #pragma unroll
    for (int i = 0; i < PP; ++i) {
        float mx = -1e30f;
        #pragma unroll
        for (int j = 0; j < PP; ++j) {
            dots[i][j] *= SCALE_ATT;
            mx = fmaxf(mx, dots[i][j]);
        }
        float s = 0.f;
        #pragma unroll
        for (int j = 0; j < PP; ++j) { dots[i][j] = __expf(dots[i][j] - mx); s += dots[i][j]; }
        float inv = 1.f / s;
        #pragma unroll
        for (int j = 0; j < PP; ++j) dots[i][j] *= inv;
    }
    #pragma unroll
    for (int i = 0; i < PP; ++i) {
        float2 o = make_float2(0.f, 0.f);
        #pragma unroll
        for (int j = 0; j < PP; ++j) {
            o.x += dots[i][j] * vv[j].x;
            o.y += dots[i][j] * vv[j].y;
        }
        int n = (b*TT + tt*PP + i)*VV + v;
        stbf2(g_ao + (size_t)n*INNER + h*DH + d0, o);
    }
}

// ---------------- gather (coalesced row copies) -----------------------------
__global__ void k_gather() {
    int idx = blockIdx.x * 256 + threadIdx.x;     // over NKTOK * 7 * 16 (uint4 of 8 bf16)
    if (idx >= NKTOK*112) return;
    int nk = idx / 112;
    int rem = idx - nk*112;
    int kp = rem >> 4, u = rem & 15;
    int v  = nk % VV;
    int rr = nk / VV;
    int tt = rr % NTP;
    int b  = rr / NTP;
    int src = ((b*TT + tt*PP + kp)*VV + v)*CC + u*8;
    *reinterpret_cast<uint4*>(g_xg + (size_t)nk*896 + kp*128 + u*8) =
        *reinterpret_cast<const uint4*>(g_xn + src);
}

// ---------------- global attention: one block per (b, h, v) ----------------
__global__ void __launch_bounds__(160) k_gattn() {
    int bid = blockIdx.x;
    int v = bid % VV;
    int rr = bid / VV;
    int h = rr & 7;
    int b = rr >> 3;
    __shared__ float ks[NTP][DH];
    __shared__ float vs[NTP][DH];
    for (int idx = threadIdx.x; idx < NTP*DH/2; idx += 160) {
        int j = idx >> 5, d2 = idx & 31;
        int nk = (b*NTP + j)*VV + v;
        size_t o = (size_t)nk*1024 + h*DH + d2*2;
        float2 kf = ldbf2(g_kv + o);
        float2 vf = ldbf2(g_kv + o + 512);
        ks[j][d2*2] = kf.x; ks[j][d2*2+1] = kf.y;
        vs[j][d2*2] = vf.x; vs[j][d2*2+1] = vf.y;
    }
    __syncthreads();
    int tid = threadIdx.x;
    if (tid >= 147) return;
    int i0 = 2*tid;
    size_t q0 = (size_t)((b*TT + i0)*VV + v)*INNER + h*DH;
    size_t q1 = q0 + (size_t)VV*INNER;

    float da[NTP], db[NTP];
    #pragma unroll
    for (int j = 0; j < NTP; ++j) { da[j] = 0.f; db[j] = 0.f; }

    for (int dchunk = 0; dchunk < 4; ++dchunk) {
        int dbase = dchunk * 16;
        float qa[16], qb[16];
        {
            uint4 u0 = *(const uint4*)(g_q + q0 + dbase);
            uint4 u1 = *(const uint4*)(g_q + q0 + dbase + 8);
            uint4 w0 = *(const uint4*)(g_q + q1 + dbase);
            uint4 w1 = *(const uint4*)(g_q + q1 + dbase + 8);
            float2 f;
            f=u2f2(u0.x); qa[0]=f.x; qa[1]=f.y;  f=u2f2(u0.y); qa[2]=f.x; qa[3]=f.y;
            f=u2f2(u0.z); qa[4]=f.x; qa[5]=f.y;  f=u2f2(u0.w); qa[6]=f.x; qa[7]=f.y;
            f=u2f2(u1.x); qa[8]=f.x; qa[9]=f.y;  f=u2f2(u1.y); qa[10]=f.x; qa[11]=f.y;
            f=u2f2(u1.z); qa[12]=f.x; qa[13]=f.y; f=u2f2(u1.w); qa[14]=f.x; qa[15]=f.y;
            f=u2f2(w0.x); qb[0]=f.x; qb[1]=f.y;  f=u2f2(w0.y); qb[2]=f.x; qb[3]=f.y;
            f=u2f2(w0.z); qb[4]=f.x; qb[5]=f.y;  f=u2f2(w0.w); qb[6]=f.x; qb[7]=f.y;
            f=u2f2(w1.x); qb[8]=f.x; qb[9]=f.y;  f=u2f2(w1.y); qb[10]=f.x; qb[11]=f.y;
            f=u2f2(w1.z); qb[12]=f.x; qb[13]=f.y; f=u2f2(w1.w); qb[14]=f.x; qb[15]=f.y;
        }
        #pragma unroll
        for (int j = 0; j < NTP; ++j) {
            #pragma unroll
            for (int dd = 0; dd < 16; ++dd) {
                float kv = ks[j][dbase + dd];
                da[j] += qa[dd] * kv;
                db[j] += qb[dd] * kv;
            }
        }
    }
    {
        float mx = -1e30f;
        #pragma unroll
        for (int j = 0; j < NTP; ++j) { da[j] *= SCALE_ATT; mx = fmaxf(mx, da[j]); }
        float s = 0.f;
        #pragma unroll
        for (int j = 0; j < NTP; ++j) { da[j] = __expf(da[j] - mx); s += da[j]; }
        float inv = 1.f / s;
        #pragma unroll
        for (int j = 0; j < NTP; ++j) da[j] *= inv;
    }
    {
        float mx = -1e30f;
        #pragma unroll
        for (int j = 0; j < NTP; ++j) { db[j] *= SCALE_ATT; mx = fmaxf(mx, db[j]); }
        float s = 0.f;
        #pragma unroll
        for (int j = 0; j < NTP; ++j) { db[j] = __expf(db[j] - mx); s += db[j]; }
        float inv = 1.f / s;
        #pragma unroll
        for (int j = 0; j < NTP; ++j) db[j] *= inv;
    }
    size_t o0 = q0, o1 = q1;   // ao has same [N,512] layout
    for (int dchunk = 0; dchunk < 4; ++dchunk) {
        int dbase = dchunk * 16;
        float oa[16], ob[16];
        #pragma unroll
        for (int dd = 0; dd < 16; ++dd) { oa[dd] = 0.f; ob[dd] = 0.f; }
        #pragma unroll
        for (int j = 0; j < NTP; ++j) {
            #pragma unroll
            for (int dd = 0; dd < 16; ++dd) {
                float vv = vs[j][dbase + dd];
                oa[dd] += da[j] * vv;
                ob[dd] += db[j] * vv;
            }
        }
        #pragma unroll
        for (int dd = 0; dd < 16; dd += 2) {
            stbf2(g_ao + o0 + dbase + dd, make_float2(oa[dd], oa[dd+1]));
            stbf2(g_ao + o1 + dbase + dd, make_float2(ob[dd], ob[dd+1]));
        }
    }
}

// ---------------- launch -----------------------------------------------------
extern "C" void kernel_launch(void* const* d_in, const int* in_sizes, int n_in,
                              void* d_out, int out_size) {
    (void)in_sizes; (void)n_in; (void)out_size;
    float* p_xT;
    __nv_bfloat16 *p_xn, *p_qkv, *p_q, *p_kv, *p_ao, *p_xg, *p_wt;
    cudaGetSymbolAddress((void**)&p_xT,  g_xT);
    cudaGetSymbolAddress((void**)&p_xn,  g_xn);
    cudaGetSymbolAddress((void**)&p_qkv, g_qkv);
    cudaGetSymbolAddress((void**)&p_q,   g_q);
    cudaGetSymbolAddress((void**)&p_kv,  g_kv);
    cudaGetSymbolAddress((void**)&p_ao,  g_ao);
    cudaGetSymbolAddress((void**)&p_xg,  g_xg);
    cudaGetSymbolAddress((void**)&p_wt,  g_wt);

    cudaFuncSetAttribute(k_gemm_bf<0>, cudaFuncAttributeMaxDynamicSharedMemorySize, GEMM_SMEM);
    cudaFuncSetAttribute(k_gemm_bf<2>, cudaFuncAttributeMaxDynamicSharedMemorySize, GEMM_SMEM);
    cudaFuncSetAttribute(k_gemm_bf<3>, cudaFuncAttributeMaxDynamicSharedMemorySize, GEMM_SMEM);

    const float* x      = (const float*)d_in[0];
    const float* ln1_g  = (const float*)d_in[1];
    const float* ln1_b  = (const float*)d_in[2];
    const float* la_wq  = (const float*)d_in[3];
    const float* la_wkv = (const float*)d_in[4];
    const float* la_wo  = (const float*)d_in[5];
    const float* la_bo  = (const float*)d_in[6];
    const float* ln2_g  = (const float*)d_in[7];
    const float* ln2_b  = (const float*)d_in[8];
    const float* ff1_w1 = (const float*)d_in[9];
    const float* ff1_b1 = (const float*)d_in[10];
    const float* ff1_w2 = (const float*)d_in[11];
    const float* ff1_b2 = (const float*)d_in[12];
    const float* ln3_g  = (const float*)d_in[13];
    const float* ln3_b  = (const float*)d_in[14];
    const float* ga_wq  = (const float*)d_in[15];
    const float* ga_wkv = (const float*)d_in[16];
    const float* ga_wo  = (const float*)d_in[17];
    const float* ga_bo  = (const float*)d_in[18];
    const float* ln4_g  = (const float*)d_in[19];
    const float* ln4_b  = (const float*)d_in[20];
    const float* ff2_w1 = (const float*)d_in[21];
    const float* ff2_b1 = (const float*)d_in[22];
    const float* ff2_w2 = (const float*)d_in[23];
    const float* ff2_b2 = (const float*)d_in[24];

    // weight prep: 2 launches
    for (int l = 0; l < 2; ++l) {
        k_wprep<<<4096, 256>>>(
            la_wq  + (size_t)l*CC*INNER,      la_wkv + (size_t)l*CC*2*INNER,
            la_wo  + (size_t)l*INNER*CC,      ff1_w1 + (size_t)l*CC*512,
            ff1_w2 + (size_t)l*512*CC,        ga_wq  + (size_t)l*CC*INNER,
            ga_wkv + (size_t)l*CC*PP*2*INNER, ga_wo  + (size_t)l*INNER*CC,
            ff2_w1 + (size_t)l*CC*512,        ff2_w2 + (size_t)l*512*CC,
            p_wt + (size_t)l*WT_LSZ);
    }

    const int rowTiles  = (NTOK  + 127) / 128;   // 919
    const int rowTilesG = (NKTOK + 127) / 128;   // 132
    const int lnGrid = NTOK / 8;                 // 14700

    k_tin<<<BB*TT, 256>>>(x);
    for (int l = 0; l < 2; ++l) {
        __nv_bfloat16* wb = p_wt + (size_t)l*WT_LSZ;
        // --- local attention block ---
        k_ln<<<lnGrid, 256>>>(ln1_g + l*CC, ln1_b + l*CC);
        k_gemm_bf<0><<<dim3(12, rowTiles), 256, GEMM_SMEM>>>(p_xn, wb + OFF_LQKV, nullptr, nullptr, p_qkv, NTOK, 128, 1536);
        k_lattn<<<NKTOK, 256>>>();
        k_gemm_bf<3><<<dim3(1, rowTiles), 256, GEMM_SMEM>>>(p_ao, wb + OFF_LWO, la_bo + l*CC, p_xT, p_xT, NTOK, 512, 128);
        // --- ff1 ---
        k_ln<<<lnGrid, 256>>>(ln2_g + l*CC, ln2_b + l*CC);
        k_gemm_bf<2><<<dim3(4, rowTiles), 256, GEMM_SMEM>>>(p_xn, wb + OFF_F1A, ff1_b1 + l*512, nullptr, p_ao, NTOK, 128, 512);
        k_gemm_bf<3><<<dim3(1, rowTiles), 256, GEMM_SMEM>>>(p_ao, wb + OFF_F1B, ff1_b2 + l*CC, p_xT, p_xT, NTOK, 512, 128);
        // --- global attention block ---
        k_ln<<<lnGrid, 256>>>(ln3_g + l*CC, ln3_b + l*CC);
        k_gemm_bf<0><<<dim3(4, rowTiles), 256, GEMM_SMEM>>>(p_xn, wb + OFF_GWQ, nullptr, nullptr, p_q, NTOK, 128, 512);
        k_gather<<<(NKTOK*112 + 255)/256, 256>>>();
        k_gemm_bf<0><<<dim3(8, rowTilesG), 256, GEMM_SMEM>>>(p_xg, wb + OFF_GWKV, nullptr, nullptr, p_kv, NKTOK, 896, 1024);
        k_gattn<<<BB*NHEAD*VV, 160>>>();
        k_gemm_bf<3><<<dim3(1, rowTiles), 256, GEMM_SMEM>>>(p_ao, wb + OFF_GWO, ga_bo + l*CC, p_xT, p_xT, NTOK, 512, 128);
        // --- ff2 ---
        k_ln<<<lnGrid, 256>>>(ln4_g + l*CC, ln4_b + l*CC);
        k_gemm_bf<2><<<dim3(4, rowTiles), 256, GEMM_SMEM>>>(p_xn, wb + OFF_F2A, ff2_b1 + l*512, nullptr, p_ao, NTOK, 128, 512);
        k_gemm_bf<3><<<dim3(1, rowTiles), 256, GEMM_SMEM>>>(p_ao, wb + OFF_F2B, ff2_b2 + l*CC, p_xT, p_xT, NTOK, 512, 128);
    }
    k_tout<<<BB*TT, 256>>>((float*)d_out);
}